// round 7
// baseline (speedup 1.0000x reference)
#include <cuda_runtime.h>

// ---------------- problem constants ----------------
#define NN    20000
#define EE    240000
#define ETOT  (EE + NN)        // edges + self loops = 260000
#define GG    64
#define FF    768
#define H1c   128
#define PEc   32
#define DDc   160              // H1 + PE
#define NHEAD 5
#define HCc   800              // NHEAD * DDc
#define H2c   128
#define OUTc  16
#define NEG_SLOPE 0.2f

// ---------------- device scratch (static, no allocs) ----------------
__device__ float d_h   [NN * DDc];
__device__ float d_xl  [NN * HCc];
__device__ float d_xr  [NN * HCc];
__device__ float d_g1  [NN * HCc];
__device__ float d_hg  [NN * HCc];
__device__ float d_g2  [NN * HCc];
__device__ float d_dinv[NN];
__device__ int   d_cnt [NN];
__device__ int   d_rowptr[NN + 1];
__device__ int   d_csrc[ETOT];
__device__ int   d_gstart[GG + 1];
__device__ float d_pool[GG * 2 * HCc];

// ---------------- CSR build ----------------
__global__ void k_zero_cnt() {
    int i = blockIdx.x * blockDim.x + threadIdx.x;
    if (i < NN) d_cnt[i] = 0;
}

__global__ void k_count(const int* __restrict__ ei) {
    int e = blockIdx.x * blockDim.x + threadIdx.x;
    if (e >= ETOT) return;
    int dst = (e < EE) ? ei[EE + e] : (e - EE);
    atomicAdd(&d_cnt[dst], 1);
}

__global__ void k_scan() {
    __shared__ int sh[1024];
    __shared__ int soff;
    int t = threadIdx.x;
    if (t == 0) soff = 0;
    __syncthreads();
    for (int base = 0; base < NN; base += 1024) {
        int i = base + t;
        int v = (i < NN) ? d_cnt[i] : 0;
        if (i < NN) {
            d_dinv[i] = rsqrtf((float)v);   // deg >= 1 (self loop)
            d_cnt[i] = 0;
        }
        sh[t] = v;
        __syncthreads();
        for (int off = 1; off < 1024; off <<= 1) {
            int add = (t >= off) ? sh[t - off] : 0;
            __syncthreads();
            sh[t] += add;
            __syncthreads();
        }
        if (i < NN) d_rowptr[i] = soff + sh[t] - v;
        __syncthreads();
        if (t == 1023) soff += sh[1023];
        __syncthreads();
    }
    if (t == 0) d_rowptr[NN] = soff;
}

__global__ void k_fill(const int* __restrict__ ei) {
    int e = blockIdx.x * blockDim.x + threadIdx.x;
    if (e >= ETOT) return;
    int src, dst;
    if (e < EE) { src = ei[e]; dst = ei[EE + e]; }
    else        { src = e - EE; dst = e - EE; }
    int pos = d_rowptr[dst] + atomicAdd(&d_cnt[dst], 1);
    d_csrc[pos] = src;
}

// ---------------- TF32 tensor-core GEMM ----------------
// CTA tile 128x128, BK=32, 256 threads, 8 warps (2m x 4n), warp tile 64x32.
// Packed-float2 fragment smem (one conflict-free LDS.64 per mma fragment),
// register-prefetch double buffering.
// Requires K % 32 == 0; lda,ldb multiples of 4; ldc even; Nc multiple of 4.
#define A_STR2 20                 // float2 per A m-row (16 + 4 pad)
#define B_STR2 132                // float2 per B (ks,kq)-row (128 + 4 pad)
#define A_F2   (128 * A_STR2)     // 2560 float2 per buffer
#define B_F2   (16 * B_STR2)      // 2112 float2 per buffer
#define SMEM_GEMM_BYTES ((2 * (A_F2 + B_F2)) * (int)sizeof(float2))  // 74752

__device__ __forceinline__ float to_tf32(float x) {
    float r;
    asm("cvt.rna.tf32.f32 %0, %1;" : "=f"(r) : "f"(x));
    return r;
}

__device__ __forceinline__ void mma_tf32(float c[4], float a0, float a1, float a2, float a3,
                                         float b0, float b1) {
    asm volatile(
        "mma.sync.aligned.m16n8k8.row.col.f32.tf32.tf32.f32 "
        "{%0,%1,%2,%3}, {%4,%5,%6,%7}, {%8,%9}, {%0,%1,%2,%3};\n"
        : "+f"(c[0]), "+f"(c[1]), "+f"(c[2]), "+f"(c[3])
        : "r"(__float_as_uint(a0)), "r"(__float_as_uint(a1)),
          "r"(__float_as_uint(a2)), "r"(__float_as_uint(a3)),
          "r"(__float_as_uint(b0)), "r"(__float_as_uint(b1)));
}

__global__ void __launch_bounds__(256)
k_gemm_tf32(const float* __restrict__ A, const float* __restrict__ B,
            const float* __restrict__ bias, float* __restrict__ C,
            int M, int Nc, int K, int lda, int ldb, int ldc, int relu)
{
    extern __shared__ float2 smem2[];
    float2* Af2 = smem2;                 // [2][A_F2]
    float2* Bf2 = smem2 + 2 * A_F2;      // [2][B_F2]

    const int t    = threadIdx.x;
    const int lane = t & 31;
    const int warp = t >> 5;
    const int wm   = warp >> 2;          // 0..1 -> m offset wm*64
    const int wn   = warp & 3;           // 0..3 -> n offset wn*32
    const int g    = lane >> 2;
    const int kq   = lane & 3;

    const int m0 = blockIdx.y * 128, n0 = blockIdx.x * 128;
    const float4 z4 = make_float4(0.f, 0.f, 0.f, 0.f);

    // loader maps
    const int acol  = t & 7;            // A k-quad 0..7
    const int abase = t >> 3;           // A row base 0..31 (+32p)
    const int aks   = acol >> 1, ae = acol & 1;
    const int bcol  = t & 31;           // B n-quad 0..31
    const int bbase = t >> 5;           // B k base 0..7 (+8p)

    float acc[4][4][4];
    #pragma unroll
    for (int i = 0; i < 4; i++)
        #pragma unroll
        for (int j = 0; j < 4; j++)
            #pragma unroll
            for (int q = 0; q < 4; q++) acc[i][j][q] = 0.f;

    const int nk = K >> 5;

    float4 ra[4], rb[4];
    // ---- prefetch tile 0 ----
    #pragma unroll
    for (int p = 0; p < 4; p++) {
        int row = abase + p * 32;
        int gm = m0 + row;
        ra[p] = (gm < M) ? *(const float4*)&A[(size_t)gm * lda + acol * 4] : z4;
    }
    #pragma unroll
    for (int p = 0; p < 4; p++) {
        int row = bbase + p * 8;
        int gn = n0 + bcol * 4;
        rb[p] = (gn < Nc) ? *(const float4*)&B[(size_t)row * ldb + gn] : z4;
    }
    // ---- store tile 0 into buffer 0 ----
    #pragma unroll
    for (int p = 0; p < 4; p++) {
        int row = abase + p * 32;
        float* dst = (float*)(Af2 + row * A_STR2 + aks * 4) + ae;
        dst[0] = to_tf32(ra[p].x); dst[2] = to_tf32(ra[p].y);
        dst[4] = to_tf32(ra[p].z); dst[6] = to_tf32(ra[p].w);
    }
    #pragma unroll
    for (int p = 0; p < 4; p++) {
        int row = bbase + p * 8;
        int ks = row >> 3, kq4 = row & 7;
        int kqq = kq4 & 3, e = kq4 >> 2;
        float* dst = (float*)(Bf2 + (ks * 4 + kqq) * B_STR2 + bcol * 4) + e;
        dst[0] = to_tf32(rb[p].x); dst[2] = to_tf32(rb[p].y);
        dst[4] = to_tf32(rb[p].z); dst[6] = to_tf32(rb[p].w);
    }
    __syncthreads();

    int cur = 0;
    for (int kt = 0; kt < nk; kt++) {
        const bool has_next = (kt + 1) < nk;
        if (has_next) {
            const int kb = (kt + 1) << 5;
            #pragma unroll
            for (int p = 0; p < 4; p++) {
                int row = abase + p * 32;
                int gm = m0 + row;
                ra[p] = (gm < M) ? *(const float4*)&A[(size_t)gm * lda + kb + acol * 4] : z4;
            }
            #pragma unroll
            for (int p = 0; p < 4; p++) {
                int row = bbase + p * 8;
                int gn = n0 + bcol * 4;
                rb[p] = (gn < Nc) ? *(const float4*)&B[(size_t)(kb + row) * ldb + gn] : z4;
            }
        }

        const float2* Ac = Af2 + cur * A_F2;
        const float2* Bc = Bf2 + cur * B_F2;
        #pragma unroll
        for (int ks = 0; ks < 4; ks++) {
            float2 pa[4][2];
            #pragma unroll
            for (int mi = 0; mi < 4; mi++) {
                int mr = wm * 64 + mi * 16;
                pa[mi][0] = Ac[(mr + g)     * A_STR2 + ks * 4 + kq];
                pa[mi][1] = Ac[(mr + 8 + g) * A_STR2 + ks * 4 + kq];
            }
            float2 pb[4];
            #pragma unroll
            for (int ni = 0; ni < 4; ni++) {
                int nc = wn * 32 + ni * 8 + g;
                pb[ni] = Bc[(ks * 4 + kq) * B_STR2 + nc];
            }
            #pragma unroll
            for (int mi = 0; mi < 4; mi++)
                #pragma unroll
                for (int ni = 0; ni < 4; ni++)
                    mma_tf32(acc[mi][ni], pa[mi][0].x, pa[mi][1].x, pa[mi][0].y, pa[mi][1].y,
                             pb[ni].x, pb[ni].y);
        }

        if (has_next) {
            const int nxt = cur ^ 1;
            float2* An = Af2 + nxt * A_F2;
            float2* Bn = Bf2 + nxt * B_F2;
            #pragma unroll
            for (int p = 0; p < 4; p++) {
                int row = abase + p * 32;
                float* dst = (float*)(An + row * A_STR2 + aks * 4) + ae;
                dst[0] = to_tf32(ra[p].x); dst[2] = to_tf32(ra[p].y);
                dst[4] = to_tf32(ra[p].z); dst[6] = to_tf32(ra[p].w);
            }
            #pragma unroll
            for (int p = 0; p < 4; p++) {
                int row = bbase + p * 8;
                int ks = row >> 3, kq4 = row & 7;
                int kqq = kq4 & 3, e = kq4 >> 2;
                float* dst = (float*)(Bn + (ks * 4 + kqq) * B_STR2 + bcol * 4) + e;
                dst[0] = to_tf32(rb[p].x); dst[2] = to_tf32(rb[p].y);
                dst[4] = to_tf32(rb[p].z); dst[6] = to_tf32(rb[p].w);
            }
            __syncthreads();
            cur = nxt;
        }
    }

    // ---- epilogue ----
    #pragma unroll
    for (int mi = 0; mi < 4; mi++) {
        #pragma unroll
        for (int half = 0; half < 2; half++) {
            int gm = m0 + wm * 64 + mi * 16 + g + half * 8;
            if (gm >= M) continue;
            #pragma unroll
            for (int ni = 0; ni < 4; ni++) {
                int gn = n0 + wn * 32 + ni * 8 + 2 * kq;
                if (gn >= Nc) continue;
                float v0 = acc[mi][ni][half * 2 + 0];
                float v1 = acc[mi][ni][half * 2 + 1];
                if (bias) { v0 += bias[gn]; v1 += bias[gn + 1]; }
                if (relu) { v0 = fmaxf(v0, 0.f); v1 = fmaxf(v1, 0.f); }
                float2 st; st.x = v0; st.y = v1;
                *(float2*)&C[(size_t)gm * ldc + gn] = st;
            }
        }
    }
}

// copy pe_enc into h[:, 128:160]
__global__ void k_pe(const float* __restrict__ pe) {
    int i = blockIdx.x * blockDim.x + threadIdx.x;
    if (i >= NN * PEc) return;
    int n = i / PEc, c = i % PEc;
    d_h[n * DDc + H1c + c] = pe[i];
}

// ---------------- fused GATv2: score + online softmax + aggregation ----------------
__global__ void __launch_bounds__(128)
k_gat_fused(const float* __restrict__ att, const float* __restrict__ gat_bias) {
    __shared__ float s_att[HCc];
    const int t = threadIdx.x;
    for (int k = t; k < HCc; k += 128) s_att[k] = att[k];
    __syncthreads();

    const int n = (blockIdx.x * 128 + t) >> 5;
    const int lane = t & 31;
    if (n >= NN) return;

    float xrr[25];
    {
        const float* xr = d_xr + (size_t)n * HCc;
        #pragma unroll
        for (int j = 0; j < 25; j++) xrr[j] = xr[lane + 32 * j];
    }

    float m[NHEAD], s[NHEAD], acc[25];
    #pragma unroll
    for (int h = 0; h < NHEAD; h++) { m[h] = -1e30f; s[h] = 0.f; }
    #pragma unroll
    for (int j = 0; j < 25; j++) acc[j] = 0.f;

    const int beg = d_rowptr[n], end = d_rowptr[n + 1];
    for (int i = beg; i < end; i++) {
        const int src = d_csrc[i];
        const float* xl = d_xl + (size_t)src * HCc;
        float xlr[25];
        #pragma unroll
        for (int j = 0; j < 25; j++) xlr[j] = xl[lane + 32 * j];

        float sc[NHEAD];
        #pragma unroll
        for (int h = 0; h < NHEAD; h++) {
            float p = 0.f;
            #pragma unroll
            for (int k5 = 0; k5 < 5; k5++) {
                int j = h * 5 + k5;
                float mm = xlr[j] + xrr[j];
                mm = (mm > 0.f) ? mm : NEG_SLOPE * mm;
                p += mm * s_att[lane + 32 * j];
            }
            #pragma unroll
            for (int off = 16; off > 0; off >>= 1)
                p += __shfl_xor_sync(0xffffffffu, p, off);
            sc[h] = p;
        }

        float scl[NHEAD], w[NHEAD];
        #pragma unroll
        for (int h = 0; h < NHEAD; h++) {
            float nm = fmaxf(m[h], sc[h]);
            scl[h] = __expf(m[h] - nm);
            w[h]   = __expf(sc[h] - nm);
            s[h] = s[h] * scl[h] + w[h];
            m[h] = nm;
        }
        #pragma unroll
        for (int j = 0; j < 25; j++) {
            const int h = j / 5;
            acc[j] = acc[j] * scl[h] + w[h] * xlr[j];
        }
    }

    float rs[NHEAD];
    #pragma unroll
    for (int h = 0; h < NHEAD; h++) rs[h] = 1.f / s[h];
    float* g1 = d_g1 + (size_t)n * HCc;
    #pragma unroll
    for (int j = 0; j < 25; j++) {
        int c = lane + 32 * j;
        g1[c] = fmaxf(acc[j] * rs[j / 5] + gat_bias[c], 0.f);
    }
}

// ---------------- GCN aggregation, gather form, float4 (one warp / dst node) -------
__global__ void k_gcn_agg(const float* __restrict__ b_gcn) {
    int n = (blockIdx.x * blockDim.x + threadIdx.x) >> 5;
    int lane = threadIdx.x & 31;
    if (n >= NN) return;
    float4 a[6];
    #pragma unroll
    for (int q = 0; q < 6; q++) a[q] = make_float4(0.f, 0.f, 0.f, 0.f);
    float at = 0.f;                      // tail channel 768 + lane
    int beg = d_rowptr[n], end = d_rowptr[n + 1];
    float dn = d_dinv[n];
    for (int i = beg; i < end; i++) {
        int src = d_csrc[i];
        float w = d_dinv[src] * dn;
        const float* hg = d_hg + (size_t)src * HCc;
        #pragma unroll
        for (int q = 0; q < 6; q++) {
            float4 v = ((const float4*)hg)[lane + 32 * q];
            a[q].x += w * v.x; a[q].y += w * v.y;
            a[q].z += w * v.z; a[q].w += w * v.w;
        }
        at += w * hg[768 + lane];
    }
    float* g2 = d_g2 + (size_t)n * HCc;
    #pragma unroll
    for (int q = 0; q < 6; q++) {
        int c = (lane + 32 * q) * 4;
        float4 b = *(const float4*)&b_gcn[c];
        float4 o;
        o.x = fmaxf(a[q].x + b.x, 0.f); o.y = fmaxf(a[q].y + b.y, 0.f);
        o.z = fmaxf(a[q].z + b.z, 0.f); o.w = fmaxf(a[q].w + b.w, 0.f);
        *(float4*)&g2[c] = o;
    }
    g2[768 + lane] = fmaxf(at + b_gcn[768 + lane], 0.f);
}

// ---------------- graph boundaries (batch sorted) ----------------
__global__ void k_gstart(const int* __restrict__ batch) {
    int g = threadIdx.x;
    if (g > GG) return;
    int lo = 0, hi = NN;
    while (lo < hi) {
        int mid = (lo + hi) >> 1;
        if (batch[mid] < g) lo = mid + 1; else hi = mid;
    }
    d_gstart[g] = lo;
}

// ---------------- pooling: weighted mean + max per graph (float4) ----------------
__global__ void __launch_bounds__(256) k_pool(const float* __restrict__ fw) {
    int g = blockIdx.x;
    int t = threadIdx.x;
    int s = d_gstart[g], e2 = d_gstart[g + 1];
    if (t >= 200) return;                       // 200 float4 = 800 channels
    float4 sum = make_float4(0.f, 0.f, 0.f, 0.f);
    float4 mx  = make_float4(0.f, 0.f, 0.f, 0.f);
    float ws = 0.f;
    for (int n = s; n < e2; n++) {
        float w = fw[n];
        ws += w;
        float4 v = ((const float4*)(d_g2 + (size_t)n * HCc))[t];
        sum.x += v.x * w; sum.y += v.y * w; sum.z += v.z * w; sum.w += v.w * w;
        mx.x = fmaxf(mx.x, v.x); mx.y = fmaxf(mx.y, v.y);
        mx.z = fmaxf(mx.z, v.z); mx.w = fmaxf(mx.w, v.w);
    }
    ws = fmaxf(ws, 1e-6f);
    float rws = 1.f / ws;
    float4 mn; mn.x = sum.x * rws; mn.y = sum.y * rws; mn.z = sum.z * rws; mn.w = sum.w * rws;
    ((float4*)(d_pool + g * 2 * HCc))[t] = mn;
    ((float4*)(d_pool + g * 2 * HCc + HCc))[t] = mx;
}

// ---------------- MLP head ----------------
__global__ void __launch_bounds__(128)
k_head(const float* __restrict__ W_fc, const float* __restrict__ b_fc,
       const float* __restrict__ W_out, const float* __restrict__ b_out,
       float* __restrict__ out)
{
    __shared__ float sp[2 * HCc];
    __shared__ float shid[H2c];
    int g = blockIdx.x, t = threadIdx.x;
    for (int k = t; k < 2 * HCc; k += 128) sp[k] = d_pool[g * 2 * HCc + k];
    __syncthreads();
    float acc = b_fc[t];
    for (int k = 0; k < 2 * HCc; k++) acc += sp[k] * W_fc[k * H2c + t];
    shid[t] = fmaxf(acc, 0.f);
    __syncthreads();
    if (t < OUTc) {
        float o = b_out[t];
        #pragma unroll
        for (int k = 0; k < H2c; k++) o += shid[k] * W_out[k * OUTc + t];
        out[g * OUTc + t] = fmaxf(o, 0.f);
    }
}

// ---------------- launch ----------------
extern "C" void kernel_launch(void* const* d_in, const int* in_sizes, int n_in,
                              void* d_out, int out_size)
{
    const float* x     = (const float*)d_in[0];
    const float* pe    = (const float*)d_in[1];
    const int*   ei    = (const int*)  d_in[2];
    const int*   batch = (const int*)  d_in[3];
    const float* fw    = (const float*)d_in[4];
    int wbase = (in_sizes[5] == 1) ? 6 : 5;
    const float* W_pre    = (const float*)d_in[wbase + 0];
    const float* b_pre    = (const float*)d_in[wbase + 1];
    const float* W_l      = (const float*)d_in[wbase + 2];
    const float* b_l      = (const float*)d_in[wbase + 3];
    const float* W_r      = (const float*)d_in[wbase + 4];
    const float* b_r      = (const float*)d_in[wbase + 5];
    const float* att      = (const float*)d_in[wbase + 6];
    const float* gat_bias = (const float*)d_in[wbase + 7];
    const float* W_gcn    = (const float*)d_in[wbase + 8];
    const float* b_gcn    = (const float*)d_in[wbase + 9];
    const float* W_fc     = (const float*)d_in[wbase + 10];
    const float* b_fc     = (const float*)d_in[wbase + 11];
    const float* W_out    = (const float*)d_in[wbase + 12];
    const float* b_out    = (const float*)d_in[wbase + 13];
    float* out = (float*)d_out;

    float* p_h  = nullptr; cudaGetSymbolAddress((void**)&p_h,  d_h);
    float* p_xl = nullptr; cudaGetSymbolAddress((void**)&p_xl, d_xl);
    float* p_xr = nullptr; cudaGetSymbolAddress((void**)&p_xr, d_xr);
    float* p_g1 = nullptr; cudaGetSymbolAddress((void**)&p_g1, d_g1);
    float* p_hg = nullptr; cudaGetSymbolAddress((void**)&p_hg, d_hg);

    static int smem_set = 0;
    if (!smem_set) {
        cudaFuncSetAttribute(k_gemm_tf32, cudaFuncAttributeMaxDynamicSharedMemorySize,
                             SMEM_GEMM_BYTES);
        smem_set = 1;
    }

    // 1: pre-FC GEMM
    {
        dim3 grid((H1c + 127) / 128, (NN + 127) / 128);
        k_gemm_tf32<<<grid, 256, SMEM_GEMM_BYTES>>>(x, W_pre, b_pre, p_h, NN, H1c, FF, FF, H1c, DDc, 1);
    }
    // 2: pe copy
    k_pe<<<(NN * PEc + 255) / 256, 256>>>(pe);
    // 3,4: x_l / x_r projections (slot 4 gets profiled by ncu)
    {
        dim3 grid((HCc + 127) / 128, (NN + 127) / 128);
        k_gemm_tf32<<<grid, 256, SMEM_GEMM_BYTES>>>(p_h, W_l, b_l, p_xl, NN, HCc, DDc, DDc, HCc, HCc, 0);
        k_gemm_tf32<<<grid, 256, SMEM_GEMM_BYTES>>>(p_h, W_r, b_r, p_xr, NN, HCc, DDc, DDc, HCc, HCc, 0);
    }
    // 5-8: CSR build
    k_zero_cnt<<<(NN + 255) / 256, 256>>>();
    k_count<<<(ETOT + 255) / 256, 256>>>(ei);
    k_scan<<<1, 1024>>>();
    k_fill<<<(ETOT + 255) / 256, 256>>>(ei);
    // 9: fused GATv2
    k_gat_fused<<<(NN * 32 + 127) / 128, 128>>>(att, gat_bias);
    // 10: GCN GEMM
    {
        dim3 grid((HCc + 127) / 128, (NN + 127) / 128);
        k_gemm_tf32<<<grid, 256, SMEM_GEMM_BYTES>>>(p_g1, W_gcn, nullptr, p_hg, NN, HCc, HCc, HCc, HCc, HCc, 0);
    }
    // 11: GCN aggregation
    k_gcn_agg<<<(NN * 32 + 255) / 256, 256>>>(b_gcn);
    // 12-14: pooling + head
    k_gstart<<<1, 128>>>(batch);
    k_pool<<<GG, 256>>>(fw);
    k_head<<<GG, 128>>>(W_fc, b_fc, W_out, b_out, out);
}

// round 10
// speedup vs baseline: 1.6683x; 1.6683x over previous
#include <cuda_runtime.h>

// ---------------- problem constants ----------------
#define NN    20000
#define EE    240000
#define ETOT  (EE + NN)        // edges + self loops = 260000
#define GG    64
#define FF    768
#define H1c   128
#define PEc   32
#define DDc   160              // H1 + PE
#define NHEAD 5
#define HCc   800              // NHEAD * DDc
#define H2c   128
#define OUTc  16
#define NEG_SLOPE 0.2f

// ---------------- device scratch (static, no allocs) ----------------
__device__ float d_h   [NN * DDc];
__device__ float d_xl  [NN * HCc];
__device__ float d_xr  [NN * HCc];
__device__ float d_g1  [NN * HCc];
__device__ float d_hg  [NN * HCc];
__device__ float d_g2  [NN * HCc];
__device__ float d_dinv[NN];
__device__ int   d_cnt [NN];
__device__ int   d_rowptr[NN + 1];
__device__ int   d_csrc[ETOT];
__device__ int   d_gstart[GG + 1];
__device__ float d_pool[GG * 2 * HCc];

// ---------------- CSR build ----------------
__global__ void k_zero_cnt() {
    int i = blockIdx.x * blockDim.x + threadIdx.x;
    if (i < NN) d_cnt[i] = 0;
}

__global__ void k_count(const int* __restrict__ ei) {
    int e = blockIdx.x * blockDim.x + threadIdx.x;
    if (e >= ETOT) return;
    int dst = (e < EE) ? ei[EE + e] : (e - EE);
    atomicAdd(&d_cnt[dst], 1);
}

__global__ void k_scan() {
    __shared__ int sh[1024];
    __shared__ int soff;
    int t = threadIdx.x;
    if (t == 0) soff = 0;
    __syncthreads();
    for (int base = 0; base < NN; base += 1024) {
        int i = base + t;
        int v = (i < NN) ? d_cnt[i] : 0;
        if (i < NN) {
            d_dinv[i] = rsqrtf((float)v);   // deg >= 1 (self loop)
            d_cnt[i] = 0;
        }
        sh[t] = v;
        __syncthreads();
        for (int off = 1; off < 1024; off <<= 1) {
            int add = (t >= off) ? sh[t - off] : 0;
            __syncthreads();
            sh[t] += add;
            __syncthreads();
        }
        if (i < NN) d_rowptr[i] = soff + sh[t] - v;
        __syncthreads();
        if (t == 1023) soff += sh[1023];
        __syncthreads();
    }
    if (t == 0) d_rowptr[NN] = soff;
}

__global__ void k_fill(const int* __restrict__ ei) {
    int e = blockIdx.x * blockDim.x + threadIdx.x;
    if (e >= ETOT) return;
    int src, dst;
    if (e < EE) { src = ei[e]; dst = ei[EE + e]; }
    else        { src = e - EE; dst = e - EE; }
    int pos = d_rowptr[dst] + atomicAdd(&d_cnt[dst], 1);
    d_csrc[pos] = src;
}

// ---------------- TF32 tensor-core GEMM ----------------
// CTA tile 128x64, BK=32, 256 threads, 8 warps (4m x 2n), warp tile 32x32.
// Packed-float2 fragments (one conflict-free LDS.64 per mma fragment),
// register-prefetch double buffering, min 2 CTAs/SM via launch bounds.
// Requires K % 32 == 0; lda,ldb multiples of 4; Nc multiple of 4; ldc even.
#define A_STR2 20                 // float2 per A m-row (16 + 4 pad)
#define B_STR2 72                 // float2 per B krow (64 + swizzle room)
#define A_F2   (128 * A_STR2)     // 2560 float2 per buffer
#define B_F2   (16 * B_STR2)      // 1152 float2 per buffer
#define SMEM_GEMM_BYTES ((2 * (A_F2 + B_F2)) * (int)sizeof(float2))   // 59392

__device__ __forceinline__ float to_tf32(float x) {
    float r;
    asm("cvt.rna.tf32.f32 %0, %1;" : "=f"(r) : "f"(x));
    return r;
}

__device__ __forceinline__ void mma_tf32(float c[4], float a0, float a1, float a2, float a3,
                                         float b0, float b1) {
    asm volatile(
        "mma.sync.aligned.m16n8k8.row.col.f32.tf32.tf32.f32 "
        "{%0,%1,%2,%3}, {%4,%5,%6,%7}, {%8,%9}, {%0,%1,%2,%3};\n"
        : "+f"(c[0]), "+f"(c[1]), "+f"(c[2]), "+f"(c[3])
        : "r"(__float_as_uint(a0)), "r"(__float_as_uint(a1)),
          "r"(__float_as_uint(a2)), "r"(__float_as_uint(a3)),
          "r"(__float_as_uint(b0)), "r"(__float_as_uint(b1)));
}

__global__ void __launch_bounds__(256, 2)
k_gemm_tf32(const float* __restrict__ A, const float* __restrict__ B,
            const float* __restrict__ bias, float* __restrict__ C,
            int M, int Nc, int K, int lda, int ldb, int ldc, int relu)
{
    extern __shared__ float2 smem2[];
    float2* Af2 = smem2;                 // [2][A_F2]: (m row)*20 + ks*4+kq -> (k, k+4)
    float2* Bf2 = smem2 + 2 * A_F2;      // [2][B_F2]: krow*72 + n + (n>>3) -> (k, k+4)

    const int t    = threadIdx.x;
    const int lane = t & 31;
    const int warp = t >> 5;
    const int wm   = warp >> 1;          // 0..3 -> m offset wm*32
    const int wn   = warp & 1;           // 0..1 -> n offset wn*32
    const int g    = lane >> 2;
    const int kq   = lane & 3;

    const int m0 = blockIdx.y * 128, n0 = blockIdx.x * 64;
    const float4 z4 = make_float4(0.f, 0.f, 0.f, 0.f);

    // loader maps
    const int acol  = t & 7;             // A k-quad 0..7
    const int abase = t >> 3;            // A row base 0..31 (+32p)
    const int aks   = acol >> 1, ae = acol & 1;
    const int bcol  = t & 15;            // B n-quad 0..15
    const int bbase = t >> 4;            // B k base 0..15 (+16p)

    float acc[2][4][4];
    #pragma unroll
    for (int i = 0; i < 2; i++)
        #pragma unroll
        for (int j = 0; j < 4; j++)
            #pragma unroll
            for (int q = 0; q < 4; q++) acc[i][j][q] = 0.f;

    const int nk = K >> 5;

    float4 ra[4], rb[2];
    // ---- prefetch tile 0 ----
    #pragma unroll
    for (int p = 0; p < 4; p++) {
        int gm = m0 + abase + p * 32;
        ra[p] = (gm < M) ? *(const float4*)&A[(size_t)gm * lda + acol * 4] : z4;
    }
    #pragma unroll
    for (int p = 0; p < 2; p++) {
        int row = bbase + p * 16;
        int gn = n0 + bcol * 4;
        rb[p] = (gn < Nc) ? *(const float4*)&B[(size_t)row * ldb + gn] : z4;
    }
    // ---- store tile 0 into buffer 0 ----
    #pragma unroll
    for (int p = 0; p < 4; p++) {
        int row = abase + p * 32;
        float* dst = (float*)(Af2 + row * A_STR2 + aks * 4) + ae;
        dst[0] = to_tf32(ra[p].x); dst[2] = to_tf32(ra[p].y);
        dst[4] = to_tf32(ra[p].z); dst[6] = to_tf32(ra[p].w);
    }
    #pragma unroll
    for (int p = 0; p < 2; p++) {
        int row = bbase + p * 16;
        int ks = row >> 3, rem = row & 7;
        int kqq = rem & 3, e = rem >> 2;
        int idx0 = (ks * 4 + kqq) * B_STR2 + bcol * 4 + (bcol >> 1);
        float* dst = (float*)(Bf2 + idx0) + e;
        dst[0] = to_tf32(rb[p].x); dst[2] = to_tf32(rb[p].y);
        dst[4] = to_tf32(rb[p].z); dst[6] = to_tf32(rb[p].w);
    }
    __syncthreads();

    int cur = 0;
    for (int kt = 0; kt < nk; kt++) {
        const bool has_next = (kt + 1) < nk;
        if (has_next) {
            const int kb = (kt + 1) << 5;
            #pragma unroll
            for (int p = 0; p < 4; p++) {
                int gm = m0 + abase + p * 32;
                ra[p] = (gm < M) ? *(const float4*)&A[(size_t)gm * lda + kb + acol * 4] : z4;
            }
            #pragma unroll
            for (int p = 0; p < 2; p++) {
                int row = bbase + p * 16;
                int gn = n0 + bcol * 4;
                rb[p] = (gn < Nc) ? *(const float4*)&B[(size_t)(kb + row) * ldb + gn] : z4;
            }
        }

        const float2* Ac = Af2 + cur * A_F2;
        const float2* Bc = Bf2 + cur * B_F2;
        #pragma unroll
        for (int ks = 0; ks < 4; ks++) {
            float2 pa[2][2];
            #pragma unroll
            for (int mi = 0; mi < 2; mi++) {
                int mr = wm * 32 + mi * 16;
                pa[mi][0] = Ac[(mr + g)     * A_STR2 + ks * 4 + kq];
                pa[mi][1] = Ac[(mr + 8 + g) * A_STR2 + ks * 4 + kq];
            }
            float2 pb[4];
            #pragma unroll
            for (int ni = 0; ni < 4; ni++) {
                // n = wn*32 + ni*8 + g ; idx = krow*72 + n + (n>>3)
                pb[ni] = Bc[(ks * 4 + kq) * B_STR2 + wn * 36 + ni * 9 + g];
            }
            #pragma unroll
            for (int mi = 0; mi < 2; mi++)
                #pragma unroll
                for (int ni = 0; ni < 4; ni++)
                    mma_tf32(acc[mi][ni], pa[mi][0].x, pa[mi][1].x, pa[mi][0].y, pa[mi][1].y,
                             pb[ni].x, pb[ni].y);
        }

        if (has_next) {
            const int nxt = cur ^ 1;
            float2* An = Af2 + nxt * A_F2;
            float2* Bn = Bf2 + nxt * B_F2;
            #pragma unroll
            for (int p = 0; p < 4; p++) {
                int row = abase + p * 32;
                float* dst = (float*)(An + row * A_STR2 + aks * 4) + ae;
                dst[0] = to_tf32(ra[p].x); dst[2] = to_tf32(ra[p].y);
                dst[4] = to_tf32(ra[p].z); dst[6] = to_tf32(ra[p].w);
            }
            #pragma unroll
            for (int p = 0; p < 2; p++) {
                int row = bbase + p * 16;
                int ks = row >> 3, rem = row & 7;
                int kqq = rem & 3, e = rem >> 2;
                int idx0 = (ks * 4 + kqq) * B_STR2 + bcol * 4 + (bcol >> 1);
                float* dst = (float*)(Bn + idx0) + e;
                dst[0] = to_tf32(rb[p].x); dst[2] = to_tf32(rb[p].y);
                dst[4] = to_tf32(rb[p].z); dst[6] = to_tf32(rb[p].w);
            }
            __syncthreads();
            cur = nxt;
        }
    }

    // ---- epilogue ----
    #pragma unroll
    for (int mi = 0; mi < 2; mi++) {
        #pragma unroll
        for (int half = 0; half < 2; half++) {
            int gm = m0 + wm * 32 + mi * 16 + g + half * 8;
            if (gm >= M) continue;
            #pragma unroll
            for (int ni = 0; ni < 4; ni++) {
                int gn = n0 + wn * 32 + ni * 8 + 2 * kq;
                if (gn >= Nc) continue;
                float v0 = acc[mi][ni][half * 2 + 0];
                float v1 = acc[mi][ni][half * 2 + 1];
                if (bias) { v0 += bias[gn]; v1 += bias[gn + 1]; }
                if (relu) { v0 = fmaxf(v0, 0.f); v1 = fmaxf(v1, 0.f); }
                float2 st; st.x = v0; st.y = v1;
                *(float2*)&C[(size_t)gm * ldc + gn] = st;
            }
        }
    }
}

// copy pe_enc into h[:, 128:160]
__global__ void k_pe(const float* __restrict__ pe) {
    int i = blockIdx.x * blockDim.x + threadIdx.x;
    if (i >= NN * PEc) return;
    int n = i / PEc, c = i % PEc;
    d_h[n * DDc + H1c + c] = pe[i];
}

// ---------------- fused GATv2: score + online softmax + aggregation ----------------
__global__ void __launch_bounds__(128)
k_gat_fused(const float* __restrict__ att, const float* __restrict__ gat_bias) {
    __shared__ float s_att[HCc];
    const int t = threadIdx.x;
    for (int k = t; k < HCc; k += 128) s_att[k] = att[k];
    __syncthreads();

    const int n = (blockIdx.x * 128 + t) >> 5;
    const int lane = t & 31;
    if (n >= NN) return;

    float xrr[25];
    {
        const float* xr = d_xr + (size_t)n * HCc;
        #pragma unroll
        for (int j = 0; j < 25; j++) xrr[j] = xr[lane + 32 * j];
    }

    float m[NHEAD], s[NHEAD], acc[25];
    #pragma unroll
    for (int h = 0; h < NHEAD; h++) { m[h] = -1e30f; s[h] = 0.f; }
    #pragma unroll
    for (int j = 0; j < 25; j++) acc[j] = 0.f;

    const int beg = d_rowptr[n], end = d_rowptr[n + 1];
    for (int i = beg; i < end; i++) {
        const int src = d_csrc[i];
        const float* xl = d_xl + (size_t)src * HCc;
        float xlr[25];
        #pragma unroll
        for (int j = 0; j < 25; j++) xlr[j] = xl[lane + 32 * j];

        float sc[NHEAD];
        #pragma unroll
        for (int h = 0; h < NHEAD; h++) {
            float p = 0.f;
            #pragma unroll
            for (int k5 = 0; k5 < 5; k5++) {
                int j = h * 5 + k5;
                float mm = xlr[j] + xrr[j];
                mm = (mm > 0.f) ? mm : NEG_SLOPE * mm;
                p += mm * s_att[lane + 32 * j];
            }
            #pragma unroll
            for (int off = 16; off > 0; off >>= 1)
                p += __shfl_xor_sync(0xffffffffu, p, off);
            sc[h] = p;
        }

        float scl[NHEAD], w[NHEAD];
        #pragma unroll
        for (int h = 0; h < NHEAD; h++) {
            float nm = fmaxf(m[h], sc[h]);
            scl[h] = __expf(m[h] - nm);
            w[h]   = __expf(sc[h] - nm);
            s[h] = s[h] * scl[h] + w[h];
            m[h] = nm;
        }
        #pragma unroll
        for (int j = 0; j < 25; j++) {
            const int h = j / 5;
            acc[j] = acc[j] * scl[h] + w[h] * xlr[j];
        }
    }

    float rs[NHEAD];
    #pragma unroll
    for (int h = 0; h < NHEAD; h++) rs[h] = 1.f / s[h];
    float* g1 = d_g1 + (size_t)n * HCc;
    #pragma unroll
    for (int j = 0; j < 25; j++) {
        int c = lane + 32 * j;
        g1[c] = fmaxf(acc[j] * rs[j / 5] + gat_bias[c], 0.f);
    }
}

// ---------------- GCN aggregation, gather form, float4 (one warp / dst node) -------
__global__ void k_gcn_agg(const float* __restrict__ b_gcn) {
    int n = (blockIdx.x * blockDim.x + threadIdx.x) >> 5;
    int lane = threadIdx.x & 31;
    if (n >= NN) return;
    float4 a[6];
    #pragma unroll
    for (int q = 0; q < 6; q++) a[q] = make_float4(0.f, 0.f, 0.f, 0.f);
    float at = 0.f;                      // tail channel 768 + lane
    int beg = d_rowptr[n], end = d_rowptr[n + 1];
    float dn = d_dinv[n];
    for (int i = beg; i < end; i++) {
        int src = d_csrc[i];
        float w = d_dinv[src] * dn;
        const float* hg = d_hg + (size_t)src * HCc;
        #pragma unroll
        for (int q = 0; q < 6; q++) {
            float4 v = ((const float4*)hg)[lane + 32 * q];
            a[q].x += w * v.x; a[q].y += w * v.y;
            a[q].z += w * v.z; a[q].w += w * v.w;
        }
        at += w * hg[768 + lane];
    }
    float* g2 = d_g2 + (size_t)n * HCc;
    #pragma unroll
    for (int q = 0; q < 6; q++) {
        int c = (lane + 32 * q) * 4;
        float4 b = *(const float4*)&b_gcn[c];
        float4 o;
        o.x = fmaxf(a[q].x + b.x, 0.f); o.y = fmaxf(a[q].y + b.y, 0.f);
        o.z = fmaxf(a[q].z + b.z, 0.f); o.w = fmaxf(a[q].w + b.w, 0.f);
        *(float4*)&g2[c] = o;
    }
    g2[768 + lane] = fmaxf(at + b_gcn[768 + lane], 0.f);
}

// ---------------- graph boundaries (batch sorted) ----------------
__global__ void k_gstart(const int* __restrict__ batch) {
    int g = threadIdx.x;
    if (g > GG) return;
    int lo = 0, hi = NN;
    while (lo < hi) {
        int mid = (lo + hi) >> 1;
        if (batch[mid] < g) lo = mid + 1; else hi = mid;
    }
    d_gstart[g] = lo;
}

// ---------------- pooling: weighted mean + max per graph (float4) ----------------
__global__ void __launch_bounds__(256) k_pool(const float* __restrict__ fw) {
    int g = blockIdx.x;
    int t = threadIdx.x;
    int s = d_gstart[g], e2 = d_gstart[g + 1];
    if (t >= 200) return;                       // 200 float4 = 800 channels
    float4 sum = make_float4(0.f, 0.f, 0.f, 0.f);
    float4 mx  = make_float4(0.f, 0.f, 0.f, 0.f);
    float ws = 0.f;
    for (int n = s; n < e2; n++) {
        float w = fw[n];
        ws += w;
        float4 v = ((const float4*)(d_g2 + (size_t)n * HCc))[t];
        sum.x += v.x * w; sum.y += v.y * w; sum.z += v.z * w; sum.w += v.w * w;
        mx.x = fmaxf(mx.x, v.x); mx.y = fmaxf(mx.y, v.y);
        mx.z = fmaxf(mx.z, v.z); mx.w = fmaxf(mx.w, v.w);
    }
    ws = fmaxf(ws, 1e-6f);
    float rws = 1.f / ws;
    float4 mn; mn.x = sum.x * rws; mn.y = sum.y * rws; mn.z = sum.z * rws; mn.w = sum.w * rws;
    ((float4*)(d_pool + g * 2 * HCc))[t] = mn;
    ((float4*)(d_pool + g * 2 * HCc + HCc))[t] = mx;
}

// ---------------- MLP head ----------------
__global__ void __launch_bounds__(128)
k_head(const float* __restrict__ W_fc, const float* __restrict__ b_fc,
       const float* __restrict__ W_out, const float* __restrict__ b_out,
       float* __restrict__ out)
{
    __shared__ float sp[2 * HCc];
    __shared__ float shid[H2c];
    int g = blockIdx.x, t = threadIdx.x;
    for (int k = t; k < 2 * HCc; k += 128) sp[k] = d_pool[g * 2 * HCc + k];
    __syncthreads();
    float acc = b_fc[t];
    for (int k = 0; k < 2 * HCc; k++) acc += sp[k] * W_fc[k * H2c + t];
    shid[t] = fmaxf(acc, 0.f);
    __syncthreads();
    if (t < OUTc) {
        float o = b_out[t];
        #pragma unroll
        for (int k = 0; k < H2c; k++) o += shid[k] * W_out[k * OUTc + t];
        out[g * OUTc + t] = fmaxf(o, 0.f);
    }
}

// ---------------- launch ----------------
extern "C" void kernel_launch(void* const* d_in, const int* in_sizes, int n_in,
                              void* d_out, int out_size)
{
    const float* x     = (const float*)d_in[0];
    const float* pe    = (const float*)d_in[1];
    const int*   ei    = (const int*)  d_in[2];
    const int*   batch = (const int*)  d_in[3];
    const float* fw    = (const float*)d_in[4];
    int wbase = (in_sizes[5] == 1) ? 6 : 5;
    const float* W_pre    = (const float*)d_in[wbase + 0];
    const float* b_pre    = (const float*)d_in[wbase + 1];
    const float* W_l      = (const float*)d_in[wbase + 2];
    const float* b_l      = (const float*)d_in[wbase + 3];
    const float* W_r      = (const float*)d_in[wbase + 4];
    const float* b_r      = (const float*)d_in[wbase + 5];
    const float* att      = (const float*)d_in[wbase + 6];
    const float* gat_bias = (const float*)d_in[wbase + 7];
    const float* W_gcn    = (const float*)d_in[wbase + 8];
    const float* b_gcn    = (const float*)d_in[wbase + 9];
    const float* W_fc     = (const float*)d_in[wbase + 10];
    const float* b_fc     = (const float*)d_in[wbase + 11];
    const float* W_out    = (const float*)d_in[wbase + 12];
    const float* b_out    = (const float*)d_in[wbase + 13];
    float* out = (float*)d_out;

    float* p_h  = nullptr; cudaGetSymbolAddress((void**)&p_h,  d_h);
    float* p_xl = nullptr; cudaGetSymbolAddress((void**)&p_xl, d_xl);
    float* p_xr = nullptr; cudaGetSymbolAddress((void**)&p_xr, d_xr);
    float* p_g1 = nullptr; cudaGetSymbolAddress((void**)&p_g1, d_g1);
    float* p_hg = nullptr; cudaGetSymbolAddress((void**)&p_hg, d_hg);

    static int smem_set = 0;
    if (!smem_set) {
        cudaFuncSetAttribute(k_gemm_tf32, cudaFuncAttributeMaxDynamicSharedMemorySize,
                             SMEM_GEMM_BYTES);
        smem_set = 1;
    }

    // 1: pre-FC GEMM
    {
        dim3 grid((H1c + 63) / 64, (NN + 127) / 128);
        k_gemm_tf32<<<grid, 256, SMEM_GEMM_BYTES>>>(x, W_pre, b_pre, p_h, NN, H1c, FF, FF, H1c, DDc, 1);
    }
    // 2: pe copy
    k_pe<<<(NN * PEc + 255) / 256, 256>>>(pe);
    // 3,4: x_l / x_r projections (slot 4 gets profiled by ncu)
    {
        dim3 grid((HCc + 63) / 64, (NN + 127) / 128);
        k_gemm_tf32<<<grid, 256, SMEM_GEMM_BYTES>>>(p_h, W_l, b_l, p_xl, NN, HCc, DDc, DDc, HCc, HCc, 0);
        k_gemm_tf32<<<grid, 256, SMEM_GEMM_BYTES>>>(p_h, W_r, b_r, p_xr, NN, HCc, DDc, DDc, HCc, HCc, 0);
    }
    // 5-8: CSR build
    k_zero_cnt<<<(NN + 255) / 256, 256>>>();
    k_count<<<(ETOT + 255) / 256, 256>>>(ei);
    k_scan<<<1, 1024>>>();
    k_fill<<<(ETOT + 255) / 256, 256>>>(ei);
    // 9: fused GATv2
    k_gat_fused<<<(NN * 32 + 127) / 128, 128>>>(att, gat_bias);
    // 10: GCN GEMM
    {
        dim3 grid((HCc + 63) / 64, (NN + 127) / 128);
        k_gemm_tf32<<<grid, 256, SMEM_GEMM_BYTES>>>(p_g1, W_gcn, nullptr, p_hg, NN, HCc, HCc, HCc, HCc, HCc, 0);
    }
    // 11: GCN aggregation
    k_gcn_agg<<<(NN * 32 + 255) / 256, 256>>>(b_gcn);
    // 12-14: pooling + head
    k_gstart<<<1, 128>>>(batch);
    k_pool<<<GG, 256>>>(fw);
    k_head<<<GG, 128>>>(W_fc, b_fc, W_out, b_out, out);
}

// round 12
// speedup vs baseline: 1.8994x; 1.1386x over previous
#include <cuda_runtime.h>
#include <cuda_fp16.h>
#include <cstdint>

// ---------------- problem constants ----------------
#define NN    20000
#define EE    240000
#define ETOT  (EE + NN)        // edges + self loops = 260000
#define GG    64
#define FF    768
#define H1c   128
#define PEc   32
#define DDc   160              // H1 + PE
#define NHEAD 5
#define HCc   800              // NHEAD * DDc
#define H2c   128
#define OUTc  16
#define NEG_SLOPE 0.2f
#define NPAD  896              // padded N for HCc-wide weights (13*64=832 <= 896)

// ---------------- device scratch (static, no allocs) ----------------
__device__ __align__(16) float d_h   [NN * DDc];
__device__ __align__(16) float d_xl  [NN * HCc];
__device__ __align__(16) float d_xr  [NN * HCc];
__device__ __align__(16) float d_g1  [NN * HCc];
__device__ __align__(16) float d_hg  [NN * HCc];
__device__ __align__(16) float d_g2  [NN * HCc];
__device__ float d_dinv[NN];
__device__ int   d_cnt [NN];
__device__ int   d_rowptr[NN + 1];
__device__ int   d_csrc[ETOT];
__device__ int   d_gstart[GG + 1];
__device__ float d_pool[GG * 2 * HCc];

// transposed fp16 weights: [Npad][K] row-major
__device__ __align__(16) __half d_wpre[128 * FF];
__device__ __align__(16) __half d_wl  [NPAD * DDc];
__device__ __align__(16) __half d_wr  [NPAD * DDc];
__device__ __align__(16) __half d_wg  [NPAD * HCc];

// ---------------- CSR build ----------------
__global__ void k_zero_cnt() {
    int i = blockIdx.x * blockDim.x + threadIdx.x;
    if (i < NN) d_cnt[i] = 0;
}

__global__ void k_count(const int* __restrict__ ei) {
    int e = blockIdx.x * blockDim.x + threadIdx.x;
    if (e >= ETOT) return;
    int dst = (e < EE) ? ei[EE + e] : (e - EE);
    atomicAdd(&d_cnt[dst], 1);
}

__global__ void k_scan() {
    __shared__ int sh[1024];
    __shared__ int soff;
    int t = threadIdx.x;
    if (t == 0) soff = 0;
    __syncthreads();
    for (int base = 0; base < NN; base += 1024) {
        int i = base + t;
        int v = (i < NN) ? d_cnt[i] : 0;
        if (i < NN) {
            d_dinv[i] = rsqrtf((float)v);   // deg >= 1 (self loop)
            d_cnt[i] = 0;
        }
        sh[t] = v;
        __syncthreads();
        for (int off = 1; off < 1024; off <<= 1) {
            int add = (t >= off) ? sh[t - off] : 0;
            __syncthreads();
            sh[t] += add;
            __syncthreads();
        }
        if (i < NN) d_rowptr[i] = soff + sh[t] - v;
        __syncthreads();
        if (t == 1023) soff += sh[1023];
        __syncthreads();
    }
    if (t == 0) d_rowptr[NN] = soff;
}

__global__ void k_fill(const int* __restrict__ ei) {
    int e = blockIdx.x * blockDim.x + threadIdx.x;
    if (e >= ETOT) return;
    int src, dst;
    if (e < EE) { src = ei[e]; dst = ei[EE + e]; }
    else        { src = e - EE; dst = e - EE; }
    int pos = d_rowptr[dst] + atomicAdd(&d_cnt[dst], 1);
    d_csrc[pos] = src;
}

// ---------------- weight prep: transpose to fp16 ----------------
// W [K, Nc] f32 -> Wt [Npad, K] fp16 (zero-padded rows)
__global__ void k_prep(const float* __restrict__ W, __half* __restrict__ Wt,
                       int K, int Nc, int Npad) {
    __shared__ float tile[32][33];
    int k0 = blockIdx.x * 32, n0 = blockIdx.y * 32;
    int tx = threadIdx.x, ty = threadIdx.y;
    #pragma unroll
    for (int j = 0; j < 32; j += 8) {
        int k = k0 + ty + j, n = n0 + tx;
        tile[ty + j][tx] = (k < K && n < Nc) ? W[(size_t)k * Nc + n] : 0.f;
    }
    __syncthreads();
    #pragma unroll
    for (int j = 0; j < 32; j += 8) {
        int n = n0 + ty + j, k = k0 + tx;
        if (n < Npad && k < K)
            Wt[(size_t)n * K + k] = __float2half_rn(tile[tx][ty + j]);
    }
}

// ---------------- fp16 tensor-core GEMM ----------------
// C[M,Nc] = A[M,K]@W (+bias)(+relu); W pre-transposed fp16 [Npad][K].
// CTA tile 128x64, BK=32, 256 threads, 8 warps (4m x 2n), warp tile 32x32,
// mma m16n8k16, packed uint2 fragments (1 LDS.64 per fragment, conflict-free),
// register-prefetch double buffering, static smem, 2 CTAs/SM.
// Requires K % 32 == 0; lda mult of 4; Nc mult of 4; ldc even.
#define ASTR 12                  // uint2 per A m-row (8 used + 4 pad)
#define BSTR 68                  // uint2 per B k-row (64 used + 4 pad)

__device__ __forceinline__ uint32_t pk2h(float a, float b) {
    __half2 h = __floats2half2_rn(a, b);
    return *(uint32_t*)&h;
}

__device__ __forceinline__ void mma_f16(float c[4], uint32_t a0, uint32_t a1,
                                        uint32_t a2, uint32_t a3,
                                        uint32_t b0, uint32_t b1) {
    asm volatile(
        "mma.sync.aligned.m16n8k16.row.col.f32.f16.f16.f32 "
        "{%0,%1,%2,%3}, {%4,%5,%6,%7}, {%8,%9}, {%0,%1,%2,%3};\n"
        : "+f"(c[0]), "+f"(c[1]), "+f"(c[2]), "+f"(c[3])
        : "r"(a0), "r"(a1), "r"(a2), "r"(a3), "r"(b0), "r"(b1));
}

__global__ void __launch_bounds__(256, 2)
k_gemm_f16(const float* __restrict__ A, const __half* __restrict__ BT,
           const float* __restrict__ bias, float* __restrict__ C,
           int M, int Nc, int K, int lda, int ldc, int relu)
{
    // As[buf][row*ASTR + s*4 + kq] = uint2{ pair(16s+2kq), pair(16s+2kq+8) } of row
    // Bs[buf][(s*4+kq)*BSTR + n]   = uint2{ pairB(16s+2kq, n), pairB(16s+2kq+8, n) }
    __shared__ uint2 As[2][128 * ASTR];
    __shared__ uint2 Bs[2][8 * BSTR];

    const int t    = threadIdx.x;
    const int lane = t & 31;
    const int warp = t >> 5;
    const int wm   = warp >> 1;          // 0..3 -> m offset wm*32
    const int wn   = warp & 1;           // 0..1 -> n offset wn*32
    const int g    = lane >> 2;
    const int kq   = lane & 3;

    const int m0 = blockIdx.y * 128, n0 = blockIdx.x * 64;
    const float4 z4 = make_float4(0.f, 0.f, 0.f, 0.f);

    // fill maps
    const int ar = t >> 1, asb = t & 1;          // A: row 0..127, s 0..1
    const int bn = t >> 1, bsb = t & 1;          // B: n 0..63, s 0..1 (t < 128)
    const bool do_b = (t < 128);
    const bool a_ok = (m0 + ar) < M;

    float acc[2][4][4];
    #pragma unroll
    for (int i = 0; i < 2; i++)
        #pragma unroll
        for (int j = 0; j < 4; j++)
            #pragma unroll
            for (int q = 0; q < 4; q++) acc[i][j][q] = 0.f;

    const int nk = K >> 5;
    const float* arow = A + (size_t)(m0 + ar) * lda + asb * 16;
    const __half* brow = BT + (size_t)(n0 + bn) * K + bsb * 16;

    float4 ra[4];
    uint4 rb0, rb1;
    // ---- prefetch tile 0 ----
    #pragma unroll
    for (int q = 0; q < 4; q++)
        ra[q] = a_ok ? *(const float4*)(arow + q * 4) : z4;
    if (do_b) {
        rb0 = *(const uint4*)(brow);
        rb1 = *(const uint4*)(brow + 8);
    }
    // ---- store tile 0 into buffer 0 ----
    {
        uint32_t p[8];
        #pragma unroll
        for (int q = 0; q < 4; q++) {
            p[2 * q]     = pk2h(ra[q].x, ra[q].y);
            p[2 * q + 1] = pk2h(ra[q].z, ra[q].w);
        }
        uint4 u0 = make_uint4(p[0], p[4], p[1], p[5]);
        uint4 u1 = make_uint4(p[2], p[6], p[3], p[7]);
        *(uint4*)&As[0][ar * ASTR + asb * 4]     = u0;
        *(uint4*)&As[0][ar * ASTR + asb * 4 + 2] = u1;
        if (do_b) {
            const uint32_t* q0 = (const uint32_t*)&rb0;
            const uint32_t* q1 = (const uint32_t*)&rb1;
            #pragma unroll
            for (int k4 = 0; k4 < 4; k4++)
                Bs[0][(bsb * 4 + k4) * BSTR + bn] = make_uint2(q0[k4], q1[k4]);
        }
    }
    __syncthreads();

    int cur = 0;
    for (int kt = 0; kt < nk; kt++) {
        const bool has_next = (kt + 1) < nk;
        if (has_next) {
            const int kb = (kt + 1) << 5;
            #pragma unroll
            for (int q = 0; q < 4; q++)
                ra[q] = a_ok ? *(const float4*)(arow + kb + q * 4) : z4;
            if (do_b) {
                rb0 = *(const uint4*)(brow + kb);
                rb1 = *(const uint4*)(brow + kb + 8);
            }
        }

        // ---- compute 2 k16 steps ----
        #pragma unroll
        for (int ks = 0; ks < 2; ks++) {
            uint2 pa[2][2];
            #pragma unroll
            for (int mi = 0; mi < 2; mi++) {
                int mr = wm * 32 + mi * 16;
                pa[mi][0] = As[cur][(mr + g)     * ASTR + ks * 4 + kq];
                pa[mi][1] = As[cur][(mr + 8 + g) * ASTR + ks * 4 + kq];
            }
            uint2 pb[4];
            #pragma unroll
            for (int ni = 0; ni < 4; ni++)
                pb[ni] = Bs[cur][(ks * 4 + kq) * BSTR + wn * 32 + ni * 8 + g];
            #pragma unroll
            for (int mi = 0; mi < 2; mi++)
                #pragma unroll
                for (int ni = 0; ni < 4; ni++)
                    mma_f16(acc[mi][ni], pa[mi][0].x, pa[mi][1].x,
                            pa[mi][0].y, pa[mi][1].y, pb[ni].x, pb[ni].y);
        }

        if (has_next) {
            const int nxt = cur ^ 1;
            uint32_t p[8];
            #pragma unroll
            for (int q = 0; q < 4; q++) {
                p[2 * q]     = pk2h(ra[q].x, ra[q].y);
                p[2 * q + 1] = pk2h(ra[q].z, ra[q].w);
            }
            uint4 u0 = make_uint4(p[0], p[4], p[1], p[5]);
            uint4 u1 = make_uint4(p[2], p[6], p[3], p[7]);
            __syncthreads();
            *(uint4*)&As[nxt][ar * ASTR + asb * 4]     = u0;
            *(uint4*)&As[nxt][ar * ASTR + asb * 4 + 2] = u1;
            if (do_b) {
                const uint32_t* q0 = (const uint32_t*)&rb0;
                const uint32_t* q1 = (const uint32_t*)&rb1;
                #pragma unroll
                for (int k4 = 0; k4 < 4; k4++)
                    Bs[nxt][(bsb * 4 + k4) * BSTR + bn] = make_uint2(q0[k4], q1[k4]);
            }
            __syncthreads();
            cur = nxt;
        }
    }

    // ---- epilogue ----
    #pragma unroll
    for (int mi = 0; mi < 2; mi++) {
        #pragma unroll
        for (int half = 0; half < 2; half++) {
            int gm = m0 + wm * 32 + mi * 16 + g + half * 8;
            if (gm >= M) continue;
            #pragma unroll
            for (int ni = 0; ni < 4; ni++) {
                int gn = n0 + wn * 32 + ni * 8 + 2 * kq;
                if (gn >= Nc) continue;
                float v0 = acc[mi][ni][half * 2 + 0];
                float v1 = acc[mi][ni][half * 2 + 1];
                if (bias) { v0 += bias[gn]; v1 += bias[gn + 1]; }
                if (relu) { v0 = fmaxf(v0, 0.f); v1 = fmaxf(v1, 0.f); }
                float2 st; st.x = v0; st.y = v1;
                *(float2*)&C[(size_t)gm * ldc + gn] = st;
            }
        }
    }
}

// copy pe_enc into h[:, 128:160]
__global__ void k_pe(const float* __restrict__ pe) {
    int i = blockIdx.x * blockDim.x + threadIdx.x;
    if (i >= NN * PEc) return;
    int n = i / PEc, c = i % PEc;
    d_h[n * DDc + H1c + c] = pe[i];
}

// ---------------- fused GATv2: score + online softmax + aggregation ----------------
__global__ void __launch_bounds__(128)
k_gat_fused(const float* __restrict__ att, const float* __restrict__ gat_bias) {
    __shared__ float s_att[HCc];
    const int t = threadIdx.x;
    for (int k = t; k < HCc; k += 128) s_att[k] = att[k];
    __syncthreads();

    const int n = (blockIdx.x * 128 + t) >> 5;
    const int lane = t & 31;
    if (n >= NN) return;

    float xrr[25];
    {
        const float* xr = d_xr + (size_t)n * HCc;
        #pragma unroll
        for (int j = 0; j < 25; j++) xrr[j] = xr[lane + 32 * j];
    }

    float m[NHEAD], s[NHEAD], acc[25];
    #pragma unroll
    for (int h = 0; h < NHEAD; h++) { m[h] = -1e30f; s[h] = 0.f; }
    #pragma unroll
    for (int j = 0; j < 25; j++) acc[j] = 0.f;

    const int beg = d_rowptr[n], end = d_rowptr[n + 1];
    for (int i = beg; i < end; i++) {
        const int src = d_csrc[i];
        const float* xl = d_xl + (size_t)src * HCc;
        float xlr[25];
        #pragma unroll
        for (int j = 0; j < 25; j++) xlr[j] = xl[lane + 32 * j];

        float sc[NHEAD];
        #pragma unroll
        for (int h = 0; h < NHEAD; h++) {
            float p = 0.f;
            #pragma unroll
            for (int k5 = 0; k5 < 5; k5++) {
                int j = h * 5 + k5;
                float mm = xlr[j] + xrr[j];
                mm = (mm > 0.f) ? mm : NEG_SLOPE * mm;
                p += mm * s_att[lane + 32 * j];
            }
            #pragma unroll
            for (int off = 16; off > 0; off >>= 1)
                p += __shfl_xor_sync(0xffffffffu, p, off);
            sc[h] = p;
        }

        float scl[NHEAD], w[NHEAD];
        #pragma unroll
        for (int h = 0; h < NHEAD; h++) {
            float nm = fmaxf(m[h], sc[h]);
            scl[h] = __expf(m[h] - nm);
            w[h]   = __expf(sc[h] - nm);
            s[h] = s[h] * scl[h] + w[h];
            m[h] = nm;
        }
        #pragma unroll
        for (int j = 0; j < 25; j++) {
            const int h = j / 5;
            acc[j] = acc[j] * scl[h] + w[h] * xlr[j];
        }
    }

    float rs[NHEAD];
    #pragma unroll
    for (int h = 0; h < NHEAD; h++) rs[h] = 1.f / s[h];
    float* g1 = d_g1 + (size_t)n * HCc;
    #pragma unroll
    for (int j = 0; j < 25; j++) {
        int c = lane + 32 * j;
        g1[c] = fmaxf(acc[j] * rs[j / 5] + gat_bias[c], 0.f);
    }
}

// ---------------- GCN aggregation, gather form, float4 (one warp / dst node) -------
__global__ void k_gcn_agg(const float* __restrict__ b_gcn) {
    int n = (blockIdx.x * blockDim.x + threadIdx.x) >> 5;
    int lane = threadIdx.x & 31;
    if (n >= NN) return;
    float4 a[6];
    #pragma unroll
    for (int q = 0; q < 6; q++) a[q] = make_float4(0.f, 0.f, 0.f, 0.f);
    float at = 0.f;                      // tail channel 768 + lane
    int beg = d_rowptr[n], end = d_rowptr[n + 1];
    float dn = d_dinv[n];
    for (int i = beg; i < end; i++) {
        int src = d_csrc[i];
        float w = d_dinv[src] * dn;
        const float* hg = d_hg + (size_t)src * HCc;
        #pragma unroll
        for (int q = 0; q < 6; q++) {
            float4 v = ((const float4*)hg)[lane + 32 * q];
            a[q].x += w * v.x; a[q].y += w * v.y;
            a[q].z += w * v.z; a[q].w += w * v.w;
        }
        at += w * hg[768 + lane];
    }
    float* g2 = d_g2 + (size_t)n * HCc;
    #pragma unroll
    for (int q = 0; q < 6; q++) {
        int c = (lane + 32 * q) * 4;
        float4 b = *(const float4*)&b_gcn[c];
        float4 o;
        o.x = fmaxf(a[q].x + b.x, 0.f); o.y = fmaxf(a[q].y + b.y, 0.f);
        o.z = fmaxf(a[q].z + b.z, 0.f); o.w = fmaxf(a[q].w + b.w, 0.f);
        *(float4*)&g2[c] = o;
    }
    g2[768 + lane] = fmaxf(at + b_gcn[768 + lane], 0.f);
}

// ---------------- graph boundaries (batch sorted) ----------------
__global__ void k_gstart(const int* __restrict__ batch) {
    int g = threadIdx.x;
    if (g > GG) return;
    int lo = 0, hi = NN;
    while (lo < hi) {
        int mid = (lo + hi) >> 1;
        if (batch[mid] < g) lo = mid + 1; else hi = mid;
    }
    d_gstart[g] = lo;
}

// ---------------- pooling: weighted mean + max per graph (float4) ----------------
__global__ void __launch_bounds__(256) k_pool(const float* __restrict__ fw) {
    int g = blockIdx.x;
    int t = threadIdx.x;
    int s = d_gstart[g], e2 = d_gstart[g + 1];
    if (t >= 200) return;                       // 200 float4 = 800 channels
    float4 sum = make_float4(0.f, 0.f, 0.f, 0.f);
    float4 mx  = make_float4(0.f, 0.f, 0.f, 0.f);
    float ws = 0.f;
    for (int n = s; n < e2; n++) {
        float w = fw[n];
        ws += w;
        float4 v = ((const float4*)(d_g2 + (size_t)n * HCc))[t];
        sum.x += v.x * w; sum.y += v.y * w; sum.z += v.z * w; sum.w += v.w * w;
        mx.x = fmaxf(mx.x, v.x); mx.y = fmaxf(mx.y, v.y);
        mx.z = fmaxf(mx.z, v.z); mx.w = fmaxf(mx.w, v.w);
    }
    ws = fmaxf(ws, 1e-6f);
    float rws = 1.f / ws;
    float4 mn; mn.x = sum.x * rws; mn.y = sum.y * rws; mn.z = sum.z * rws; mn.w = sum.w * rws;
    ((float4*)(d_pool + g * 2 * HCc))[t] = mn;
    ((float4*)(d_pool + g * 2 * HCc + HCc))[t] = mx;
}

// ---------------- MLP head ----------------
__global__ void __launch_bounds__(128)
k_head(const float* __restrict__ W_fc, const float* __restrict__ b_fc,
       const float* __restrict__ W_out, const float* __restrict__ b_out,
       float* __restrict__ out)
{
    __shared__ float sp[2 * HCc];
    __shared__ float shid[H2c];
    int g = blockIdx.x, t = threadIdx.x;
    for (int k = t; k < 2 * HCc; k += 128) sp[k] = d_pool[g * 2 * HCc + k];
    __syncthreads();
    float acc = b_fc[t];
    for (int k = 0; k < 2 * HCc; k++) acc += sp[k] * W_fc[k * H2c + t];
    shid[t] = fmaxf(acc, 0.f);
    __syncthreads();
    if (t < OUTc) {
        float o = b_out[t];
        #pragma unroll
        for (int k = 0; k < H2c; k++) o += shid[k] * W_out[k * OUTc + t];
        out[g * OUTc + t] = fmaxf(o, 0.f);
    }
}

// ---------------- launch ----------------
extern "C" void kernel_launch(void* const* d_in, const int* in_sizes, int n_in,
                              void* d_out, int out_size)
{
    const float* x     = (const float*)d_in[0];
    const float* pe    = (const float*)d_in[1];
    const int*   ei    = (const int*)  d_in[2];
    const int*   batch = (const int*)  d_in[3];
    const float* fw    = (const float*)d_in[4];
    int wbase = (in_sizes[5] == 1) ? 6 : 5;
    const float* W_pre    = (const float*)d_in[wbase + 0];
    const float* b_pre    = (const float*)d_in[wbase + 1];
    const float* W_l      = (const float*)d_in[wbase + 2];
    const float* b_l      = (const float*)d_in[wbase + 3];
    const float* W_r      = (const float*)d_in[wbase + 4];
    const float* b_r      = (const float*)d_in[wbase + 5];
    const float* att      = (const float*)d_in[wbase + 6];
    const float* gat_bias = (const float*)d_in[wbase + 7];
    const float* W_gcn    = (const float*)d_in[wbase + 8];
    const float* b_gcn    = (const float*)d_in[wbase + 9];
    const float* W_fc     = (const float*)d_in[wbase + 10];
    const float* b_fc     = (const float*)d_in[wbase + 11];
    const float* W_out    = (const float*)d_in[wbase + 12];
    const float* b_out    = (const float*)d_in[wbase + 13];
    float* out = (float*)d_out;

    float* p_h  = nullptr; cudaGetSymbolAddress((void**)&p_h,  d_h);
    float* p_xl = nullptr; cudaGetSymbolAddress((void**)&p_xl, d_xl);
    float* p_xr = nullptr; cudaGetSymbolAddress((void**)&p_xr, d_xr);
    float* p_g1 = nullptr; cudaGetSymbolAddress((void**)&p_g1, d_g1);
    float* p_hg = nullptr; cudaGetSymbolAddress((void**)&p_hg, d_hg);
    __half *p_wpre, *p_wl, *p_wr, *p_wg;
    cudaGetSymbolAddress((void**)&p_wpre, d_wpre);
    cudaGetSymbolAddress((void**)&p_wl,   d_wl);
    cudaGetSymbolAddress((void**)&p_wr,   d_wr);
    cudaGetSymbolAddress((void**)&p_wg,   d_wg);

    dim3 tb(32, 8);
    // 1: pe copy
    k_pe<<<(NN * PEc + 255) / 256, 256>>>(pe);
    // 2-5: weight prep (transpose to fp16)
    k_prep<<<dim3((FF + 31) / 32, (128 + 31) / 32), tb>>>(W_pre, p_wpre, FF, H1c, 128);
    k_prep<<<dim3((DDc + 31) / 32, (NPAD + 31) / 32), tb>>>(W_l, p_wl, DDc, HCc, NPAD);
    k_prep<<<dim3((DDc + 31) / 32, (NPAD + 31) / 32), tb>>>(W_r, p_wr, DDc, HCc, NPAD);
    k_prep<<<dim3((HCc + 31) / 32, (NPAD + 31) / 32), tb>>>(W_gcn, p_wg, HCc, HCc, NPAD);
    // 6: pre-FC GEMM
    k_gemm_f16<<<dim3(2, 157), 256>>>(x, p_wpre, b_pre, p_h, NN, H1c, FF, FF, DDc, 1);
    // 7,8: x_l / x_r projections
    k_gemm_f16<<<dim3(13, 157), 256>>>(p_h, p_wl, b_l, p_xl, NN, HCc, DDc, DDc, HCc, 0);
    k_gemm_f16<<<dim3(13, 157), 256>>>(p_h, p_wr, b_r, p_xr, NN, HCc, DDc, DDc, HCc, 0);
    // 9-12: CSR build
    k_zero_cnt<<<(NN + 255) / 256, 256>>>();
    k_count<<<(ETOT + 255) / 256, 256>>>(ei);
    k_scan<<<1, 1024>>>();
    k_fill<<<(ETOT + 255) / 256, 256>>>(ei);
    // 13: fused GATv2
    k_gat_fused<<<(NN * 32 + 127) / 128, 128>>>(att, gat_bias);
    // 14: GCN GEMM
    k_gemm_f16<<<dim3(13, 157), 256>>>(p_g1, p_wg, nullptr, p_hg, NN, HCc, HCc, HCc, HCc, 0);
    // 15: GCN aggregation
    k_gcn_agg<<<(NN * 32 + 255) / 256, 256>>>(b_gcn);
    // 16-18: pooling + head
    k_gstart<<<1, 128>>>(batch);
    k_pool<<<GG, 256>>>(fw);
    k_head<<<GG, 128>>>(W_fc, b_fc, W_out, b_out, out);
}

// round 13
// speedup vs baseline: 1.9418x; 1.0223x over previous
#include <cuda_runtime.h>
#include <cuda_fp16.h>
#include <cstdint>

// ---------------- problem constants ----------------
#define NN    20000
#define EE    240000
#define ETOT  (EE + NN)        // edges + self loops = 260000
#define GG    64
#define FF    768
#define H1c   128
#define PEc   32
#define DDc   160              // H1 + PE
#define NHEAD 5
#define HCc   800              // NHEAD * DDc
#define H2c   128
#define OUTc  16
#define NEG_SLOPE 0.2f
#define NPAD  896              // padded N for HCc-wide weights (13*64=832 <= 896)

// ---------------- device scratch (static, no allocs) ----------------
__device__ __align__(16) float d_h   [NN * DDc];
__device__ __align__(16) __half d_xlh[NN * HCc];   // x_l in fp16 (gather-bound)
__device__ __align__(16) float d_xr  [NN * HCc];
__device__ __align__(16) float d_g1  [NN * HCc];
__device__ __align__(16) __half d_hgh[NN * HCc];   // hg in fp16 (gather-bound)
__device__ __align__(16) float d_g2  [NN * HCc];
__device__ float d_dinv[NN];
__device__ int   d_cnt [NN];
__device__ int   d_rowptr[NN + 1];
__device__ int   d_csrc[ETOT];
__device__ int   d_gstart[GG + 1];
__device__ float d_pool[GG * 2 * HCc];

// transposed fp16 weights: [Npad][K] row-major
__device__ __align__(16) __half d_wpre[128 * FF];
__device__ __align__(16) __half d_wl  [NPAD * DDc];
__device__ __align__(16) __half d_wr  [NPAD * DDc];
__device__ __align__(16) __half d_wg  [NPAD * HCc];

// ---------------- CSR build ----------------
__global__ void k_zero_cnt() {
    int i = blockIdx.x * blockDim.x + threadIdx.x;
    if (i < NN) d_cnt[i] = 0;
}

__global__ void k_count(const int* __restrict__ ei) {
    int e = blockIdx.x * blockDim.x + threadIdx.x;
    if (e >= ETOT) return;
    int dst = (e < EE) ? ei[EE + e] : (e - EE);
    atomicAdd(&d_cnt[dst], 1);
}

// single-block scan, thread-local chunks of 20 -> one 1024-wide block scan
__global__ void k_scan() {
    __shared__ int sh[1024];
    const int CH = 20;                        // 1024*20 = 20480 >= NN
    int t = threadIdx.x;
    int base = t * CH;
    int loc[CH];
    int sum = 0;
    #pragma unroll
    for (int i = 0; i < CH; i++) {
        int idx = base + i;
        int v = 0;
        if (idx < NN) {
            v = d_cnt[idx];
            d_dinv[idx] = rsqrtf((float)v);   // deg >= 1 (self loop)
            d_cnt[idx] = 0;
        }
        loc[i] = sum;
        sum += v;
    }
    sh[t] = sum;
    __syncthreads();
    for (int off = 1; off < 1024; off <<= 1) {
        int add = (t >= off) ? sh[t - off] : 0;
        __syncthreads();
        sh[t] += add;
        __syncthreads();
    }
    int pre = (t == 0) ? 0 : sh[t - 1];
    #pragma unroll
    for (int i = 0; i < CH; i++) {
        int idx = base + i;
        if (idx < NN) d_rowptr[idx] = pre + loc[i];
    }
    if (t == 1023) d_rowptr[NN] = sh[1023];
}

__global__ void k_fill(const int* __restrict__ ei) {
    int e = blockIdx.x * blockDim.x + threadIdx.x;
    if (e >= ETOT) return;
    int src, dst;
    if (e < EE) { src = ei[e]; dst = ei[EE + e]; }
    else        { src = e - EE; dst = e - EE; }
    int pos = d_rowptr[dst] + atomicAdd(&d_cnt[dst], 1);
    d_csrc[pos] = src;
}

// ---------------- weight prep: transpose to fp16 ----------------
__global__ void k_prep(const float* __restrict__ W, __half* __restrict__ Wt,
                       int K, int Nc, int Npad) {
    __shared__ float tile[32][33];
    int k0 = blockIdx.x * 32, n0 = blockIdx.y * 32;
    int tx = threadIdx.x, ty = threadIdx.y;
    #pragma unroll
    for (int j = 0; j < 32; j += 8) {
        int k = k0 + ty + j, n = n0 + tx;
        tile[ty + j][tx] = (k < K && n < Nc) ? W[(size_t)k * Nc + n] : 0.f;
    }
    __syncthreads();
    #pragma unroll
    for (int j = 0; j < 32; j += 8) {
        int n = n0 + ty + j, k = k0 + tx;
        if (n < Npad && k < K)
            Wt[(size_t)n * K + k] = __float2half_rn(tile[tx][ty + j]);
    }
}

// ---------------- fp16 tensor-core GEMM ----------------
// C = A[M,K]@W (+bias)(+relu); W pre-transposed fp16 [Npad][K].
// CTA 128x64, BK=32, 256 thr, 8 warps (4m x 2n), warp tile 32x32, mma m16n8k16.
// oh=1 -> C is __half (packed half2 stores), else float.
#define ASTR 12                  // uint2 per A m-row (8 used + 4 pad)
#define BSTR 68                  // uint2 per B k-row (64 used + 4 pad)

__device__ __forceinline__ uint32_t pk2h(float a, float b) {
    __half2 h = __floats2half2_rn(a, b);
    return *(uint32_t*)&h;
}

__device__ __forceinline__ void mma_f16(float c[4], uint32_t a0, uint32_t a1,
                                        uint32_t a2, uint32_t a3,
                                        uint32_t b0, uint32_t b1) {
    asm volatile(
        "mma.sync.aligned.m16n8k16.row.col.f32.f16.f16.f32 "
        "{%0,%1,%2,%3}, {%4,%5,%6,%7}, {%8,%9}, {%0,%1,%2,%3};\n"
        : "+f"(c[0]), "+f"(c[1]), "+f"(c[2]), "+f"(c[3])
        : "r"(a0), "r"(a1), "r"(a2), "r"(a3), "r"(b0), "r"(b1));
}

__global__ void __launch_bounds__(256, 2)
k_gemm_f16(const float* __restrict__ A, const __half* __restrict__ BT,
           const float* __restrict__ bias, void* __restrict__ Cv,
           int M, int Nc, int K, int lda, int ldc, int relu, int oh)
{
    __shared__ uint2 As[2][128 * ASTR];
    __shared__ uint2 Bs[2][8 * BSTR];

    const int t    = threadIdx.x;
    const int lane = t & 31;
    const int warp = t >> 5;
    const int wm   = warp >> 1;
    const int wn   = warp & 1;
    const int g    = lane >> 2;
    const int kq   = lane & 3;

    const int m0 = blockIdx.y * 128, n0 = blockIdx.x * 64;
    const float4 z4 = make_float4(0.f, 0.f, 0.f, 0.f);

    const int ar = t >> 1, asb = t & 1;
    const int bn = t >> 1, bsb = t & 1;
    const bool do_b = (t < 128);
    const bool a_ok = (m0 + ar) < M;

    float acc[2][4][4];
    #pragma unroll
    for (int i = 0; i < 2; i++)
        #pragma unroll
        for (int j = 0; j < 4; j++)
            #pragma unroll
            for (int q = 0; q < 4; q++) acc[i][j][q] = 0.f;

    const int nk = K >> 5;
    const float* arow = A + (size_t)(m0 + ar) * lda + asb * 16;
    const __half* brow = BT + (size_t)(n0 + bn) * K + bsb * 16;

    float4 ra[4];
    uint4 rb0, rb1;
    #pragma unroll
    for (int q = 0; q < 4; q++)
        ra[q] = a_ok ? *(const float4*)(arow + q * 4) : z4;
    if (do_b) {
        rb0 = *(const uint4*)(brow);
        rb1 = *(const uint4*)(brow + 8);
    }
    {
        uint32_t p[8];
        #pragma unroll
        for (int q = 0; q < 4; q++) {
            p[2 * q]     = pk2h(ra[q].x, ra[q].y);
            p[2 * q + 1] = pk2h(ra[q].z, ra[q].w);
        }
        uint4 u0 = make_uint4(p[0], p[4], p[1], p[5]);
        uint4 u1 = make_uint4(p[2], p[6], p[3], p[7]);
        *(uint4*)&As[0][ar * ASTR + asb * 4]     = u0;
        *(uint4*)&As[0][ar * ASTR + asb * 4 + 2] = u1;
        if (do_b) {
            const uint32_t* q0 = (const uint32_t*)&rb0;
            const uint32_t* q1 = (const uint32_t*)&rb1;
            #pragma unroll
            for (int k4 = 0; k4 < 4; k4++)
                Bs[0][(bsb * 4 + k4) * BSTR + bn] = make_uint2(q0[k4], q1[k4]);
        }
    }
    __syncthreads();

    int cur = 0;
    for (int kt = 0; kt < nk; kt++) {
        const bool has_next = (kt + 1) < nk;
        if (has_next) {
            const int kb = (kt + 1) << 5;
            #pragma unroll
            for (int q = 0; q < 4; q++)
                ra[q] = a_ok ? *(const float4*)(arow + kb + q * 4) : z4;
            if (do_b) {
                rb0 = *(const uint4*)(brow + kb);
                rb1 = *(const uint4*)(brow + kb + 8);
            }
        }

        #pragma unroll
        for (int ks = 0; ks < 2; ks++) {
            uint2 pa[2][2];
            #pragma unroll
            for (int mi = 0; mi < 2; mi++) {
                int mr = wm * 32 + mi * 16;
                pa[mi][0] = As[cur][(mr + g)     * ASTR + ks * 4 + kq];
                pa[mi][1] = As[cur][(mr + 8 + g) * ASTR + ks * 4 + kq];
            }
            uint2 pb[4];
            #pragma unroll
            for (int ni = 0; ni < 4; ni++)
                pb[ni] = Bs[cur][(ks * 4 + kq) * BSTR + wn * 32 + ni * 8 + g];
            #pragma unroll
            for (int mi = 0; mi < 2; mi++)
                #pragma unroll
                for (int ni = 0; ni < 4; ni++)
                    mma_f16(acc[mi][ni], pa[mi][0].x, pa[mi][1].x,
                            pa[mi][0].y, pa[mi][1].y, pb[ni].x, pb[ni].y);
        }

        if (has_next) {
            const int nxt = cur ^ 1;
            uint32_t p[8];
            #pragma unroll
            for (int q = 0; q < 4; q++) {
                p[2 * q]     = pk2h(ra[q].x, ra[q].y);
                p[2 * q + 1] = pk2h(ra[q].z, ra[q].w);
            }
            uint4 u0 = make_uint4(p[0], p[4], p[1], p[5]);
            uint4 u1 = make_uint4(p[2], p[6], p[3], p[7]);
            __syncthreads();
            *(uint4*)&As[nxt][ar * ASTR + asb * 4]     = u0;
            *(uint4*)&As[nxt][ar * ASTR + asb * 4 + 2] = u1;
            if (do_b) {
                const uint32_t* q0 = (const uint32_t*)&rb0;
                const uint32_t* q1 = (const uint32_t*)&rb1;
                #pragma unroll
                for (int k4 = 0; k4 < 4; k4++)
                    Bs[nxt][(bsb * 4 + k4) * BSTR + bn] = make_uint2(q0[k4], q1[k4]);
            }
            __syncthreads();
            cur = nxt;
        }
    }

    // ---- epilogue ----
    #pragma unroll
    for (int mi = 0; mi < 2; mi++) {
        #pragma unroll
        for (int half = 0; half < 2; half++) {
            int gm = m0 + wm * 32 + mi * 16 + g + half * 8;
            if (gm >= M) continue;
            #pragma unroll
            for (int ni = 0; ni < 4; ni++) {
                int gn = n0 + wn * 32 + ni * 8 + 2 * kq;
                if (gn >= Nc) continue;
                float v0 = acc[mi][ni][half * 2 + 0];
                float v1 = acc[mi][ni][half * 2 + 1];
                if (bias) { v0 += bias[gn]; v1 += bias[gn + 1]; }
                if (relu) { v0 = fmaxf(v0, 0.f); v1 = fmaxf(v1, 0.f); }
                if (oh) {
                    __half* Ch = (__half*)Cv;
                    *(uint32_t*)&Ch[(size_t)gm * ldc + gn] = pk2h(v0, v1);
                } else {
                    float* Cf = (float*)Cv;
                    float2 st; st.x = v0; st.y = v1;
                    *(float2*)&Cf[(size_t)gm * ldc + gn] = st;
                }
            }
        }
    }
}

// copy pe_enc into h[:, 128:160]
__global__ void k_pe(const float* __restrict__ pe) {
    int i = blockIdx.x * blockDim.x + threadIdx.x;
    if (i >= NN * PEc) return;
    int n = i / PEc, c = i % PEc;
    d_h[n * DDc + H1c + c] = pe[i];
}

// ---------------- fused GATv2: score + online softmax + aggregation ----------------
// x_l read as fp16 (half the gather bytes); x_r stays f32 (one pass).
__global__ void __launch_bounds__(128)
k_gat_fused(const float* __restrict__ att, const float* __restrict__ gat_bias) {
    __shared__ float s_att[HCc];
    const int t = threadIdx.x;
    for (int k = t; k < HCc; k += 128) s_att[k] = att[k];
    __syncthreads();

    const int n = (blockIdx.x * 128 + t) >> 5;
    const int lane = t & 31;
    if (n >= NN) return;

    float xrr[25];
    {
        const float* xr = d_xr + (size_t)n * HCc;
        #pragma unroll
        for (int j = 0; j < 25; j++) xrr[j] = xr[lane + 32 * j];
    }

    float m[NHEAD], s[NHEAD], acc[25];
    #pragma unroll
    for (int h = 0; h < NHEAD; h++) { m[h] = -1e30f; s[h] = 0.f; }
    #pragma unroll
    for (int j = 0; j < 25; j++) acc[j] = 0.f;

    const int beg = d_rowptr[n], end = d_rowptr[n + 1];
    for (int i = beg; i < end; i++) {
        const int src = d_csrc[i];
        const __half* xl = d_xlh + (size_t)src * HCc;
        float xlr[25];
        #pragma unroll
        for (int j = 0; j < 25; j++) xlr[j] = __half2float(xl[lane + 32 * j]);

        float sc[NHEAD];
        #pragma unroll
        for (int h = 0; h < NHEAD; h++) {
            float p = 0.f;
            #pragma unroll
            for (int k5 = 0; k5 < 5; k5++) {
                int j = h * 5 + k5;
                float mm = xlr[j] + xrr[j];
                mm = (mm > 0.f) ? mm : NEG_SLOPE * mm;
                p += mm * s_att[lane + 32 * j];
            }
            #pragma unroll
            for (int off = 16; off > 0; off >>= 1)
                p += __shfl_xor_sync(0xffffffffu, p, off);
            sc[h] = p;
        }

        float scl[NHEAD], w[NHEAD];
        #pragma unroll
        for (int h = 0; h < NHEAD; h++) {
            float nm = fmaxf(m[h], sc[h]);
            scl[h] = __expf(m[h] - nm);
            w[h]   = __expf(sc[h] - nm);
            s[h] = s[h] * scl[h] + w[h];
            m[h] = nm;
        }
        #pragma unroll
        for (int j = 0; j < 25; j++) {
            const int h = j / 5;
            acc[j] = acc[j] * scl[h] + w[h] * xlr[j];
        }
    }

    float rs[NHEAD];
    #pragma unroll
    for (int h = 0; h < NHEAD; h++) rs[h] = 1.f / s[h];
    float* g1 = d_g1 + (size_t)n * HCc;
    #pragma unroll
    for (int j = 0; j < 25; j++) {
        int c = lane + 32 * j;
        g1[c] = fmaxf(acc[j] * rs[j / 5] + gat_bias[c], 0.f);
    }
}

// ---------------- GCN aggregation: hg read as fp16 (half4 loads) ----------------
__global__ void k_gcn_agg(const float* __restrict__ b_gcn) {
    int n = (blockIdx.x * blockDim.x + threadIdx.x) >> 5;
    int lane = threadIdx.x & 31;
    if (n >= NN) return;
    float4 a[6];
    #pragma unroll
    for (int q = 0; q < 6; q++) a[q] = make_float4(0.f, 0.f, 0.f, 0.f);
    float at = 0.f;                      // tail channel 768 + lane
    int beg = d_rowptr[n], end = d_rowptr[n + 1];
    float dn = d_dinv[n];
    for (int i = beg; i < end; i++) {
        int src = d_csrc[i];
        float w = d_dinv[src] * dn;
        const __half* hg = d_hgh + (size_t)src * HCc;
        #pragma unroll
        for (int q = 0; q < 6; q++) {
            uint2 u = ((const uint2*)hg)[lane + 32 * q];     // 4 halves
            float2 f01 = __half22float2(*(__half2*)&u.x);
            float2 f23 = __half22float2(*(__half2*)&u.y);
            a[q].x += w * f01.x; a[q].y += w * f01.y;
            a[q].z += w * f23.x; a[q].w += w * f23.y;
        }
        at += w * __half2float(hg[768 + lane]);
    }
    float* g2 = d_g2 + (size_t)n * HCc;
    #pragma unroll
    for (int q = 0; q < 6; q++) {
        int c = (lane + 32 * q) * 4;
        float4 b = *(const float4*)&b_gcn[c];
        float4 o;
        o.x = fmaxf(a[q].x + b.x, 0.f); o.y = fmaxf(a[q].y + b.y, 0.f);
        o.z = fmaxf(a[q].z + b.z, 0.f); o.w = fmaxf(a[q].w + b.w, 0.f);
        *(float4*)&g2[c] = o;
    }
    g2[768 + lane] = fmaxf(at + b_gcn[768 + lane], 0.f);
}

// ---------------- graph boundaries (batch sorted) ----------------
__global__ void k_gstart(const int* __restrict__ batch) {
    int g = threadIdx.x;
    if (g > GG) return;
    int lo = 0, hi = NN;
    while (lo < hi) {
        int mid = (lo + hi) >> 1;
        if (batch[mid] < g) lo = mid + 1; else hi = mid;
    }
    d_gstart[g] = lo;
}

// ---------------- pooling: weighted mean + max per graph (float4) ----------------
__global__ void __launch_bounds__(256) k_pool(const float* __restrict__ fw) {
    int g = blockIdx.x;
    int t = threadIdx.x;
    int s = d_gstart[g], e2 = d_gstart[g + 1];
    if (t >= 200) return;                       // 200 float4 = 800 channels
    float4 sum = make_float4(0.f, 0.f, 0.f, 0.f);
    float4 mx  = make_float4(0.f, 0.f, 0.f, 0.f);
    float ws = 0.f;
    for (int n = s; n < e2; n++) {
        float w = fw[n];
        ws += w;
        float4 v = ((const float4*)(d_g2 + (size_t)n * HCc))[t];
        sum.x += v.x * w; sum.y += v.y * w; sum.z += v.z * w; sum.w += v.w * w;
        mx.x = fmaxf(mx.x, v.x); mx.y = fmaxf(mx.y, v.y);
        mx.z = fmaxf(mx.z, v.z); mx.w = fmaxf(mx.w, v.w);
    }
    ws = fmaxf(ws, 1e-6f);
    float rws = 1.f / ws;
    float4 mn; mn.x = sum.x * rws; mn.y = sum.y * rws; mn.z = sum.z * rws; mn.w = sum.w * rws;
    ((float4*)(d_pool + g * 2 * HCc))[t] = mn;
    ((float4*)(d_pool + g * 2 * HCc + HCc))[t] = mx;
}

// ---------------- MLP head ----------------
__global__ void __launch_bounds__(128)
k_head(const float* __restrict__ W_fc, const float* __restrict__ b_fc,
       const float* __restrict__ W_out, const float* __restrict__ b_out,
       float* __restrict__ out)
{
    __shared__ float sp[2 * HCc];
    __shared__ float shid[H2c];
    int g = blockIdx.x, t = threadIdx.x;
    for (int k = t; k < 2 * HCc; k += 128) sp[k] = d_pool[g * 2 * HCc + k];
    __syncthreads();
    float acc = b_fc[t];
    for (int k = 0; k < 2 * HCc; k++) acc += sp[k] * W_fc[k * H2c + t];
    shid[t] = fmaxf(acc, 0.f);
    __syncthreads();
    if (t < OUTc) {
        float o = b_out[t];
        #pragma unroll
        for (int k = 0; k < H2c; k++) o += shid[k] * W_out[k * OUTc + t];
        out[g * OUTc + t] = fmaxf(o, 0.f);
    }
}

// ---------------- launch ----------------
extern "C" void kernel_launch(void* const* d_in, const int* in_sizes, int n_in,
                              void* d_out, int out_size)
{
    const float* x     = (const float*)d_in[0];
    const float* pe    = (const float*)d_in[1];
    const int*   ei    = (const int*)  d_in[2];
    const int*   batch = (const int*)  d_in[3];
    const float* fw    = (const float*)d_in[4];
    int wbase = (in_sizes[5] == 1) ? 6 : 5;
    const float* W_pre    = (const float*)d_in[wbase + 0];
    const float* b_pre    = (const float*)d_in[wbase + 1];
    const float* W_l      = (const float*)d_in[wbase + 2];
    const float* b_l      = (const float*)d_in[wbase + 3];
    const float* W_r      = (const float*)d_in[wbase + 4];
    const float* b_r      = (const float*)d_in[wbase + 5];
    const float* att      = (const float*)d_in[wbase + 6];
    const float* gat_bias = (const float*)d_in[wbase + 7];
    const float* W_gcn    = (const float*)d_in[wbase + 8];
    const float* b_gcn    = (const float*)d_in[wbase + 9];
    const float* W_fc     = (const float*)d_in[wbase + 10];
    const float* b_fc     = (const float*)d_in[wbase + 11];
    const float* W_out    = (const float*)d_in[wbase + 12];
    const float* b_out    = (const float*)d_in[wbase + 13];
    float* out = (float*)d_out;

    float* p_h  = nullptr; cudaGetSymbolAddress((void**)&p_h,  d_h);
    float* p_xr = nullptr; cudaGetSymbolAddress((void**)&p_xr, d_xr);
    float* p_g1 = nullptr; cudaGetSymbolAddress((void**)&p_g1, d_g1);
    __half* p_xlh = nullptr; cudaGetSymbolAddress((void**)&p_xlh, d_xlh);
    __half* p_hgh = nullptr; cudaGetSymbolAddress((void**)&p_hgh, d_hgh);
    __half *p_wpre, *p_wl, *p_wr, *p_wg;
    cudaGetSymbolAddress((void**)&p_wpre, d_wpre);
    cudaGetSymbolAddress((void**)&p_wl,   d_wl);
    cudaGetSymbolAddress((void**)&p_wr,   d_wr);
    cudaGetSymbolAddress((void**)&p_wg,   d_wg);

    dim3 tb(32, 8);
    // 1: pe copy
    k_pe<<<(NN * PEc + 255) / 256, 256>>>(pe);
    // 2-5: weight prep (transpose to fp16)
    k_prep<<<dim3((FF + 31) / 32, (128 + 31) / 32), tb>>>(W_pre, p_wpre, FF, H1c, 128);
    k_prep<<<dim3((DDc + 31) / 32, (NPAD + 31) / 32), tb>>>(W_l, p_wl, DDc, HCc, NPAD);
    k_prep<<<dim3((DDc + 31) / 32, (NPAD + 31) / 32), tb>>>(W_r, p_wr, DDc, HCc, NPAD);
    k_prep<<<dim3((HCc + 31) / 32, (NPAD + 31) / 32), tb>>>(W_gcn, p_wg, HCc, HCc, NPAD);
    // 6: pre-FC GEMM
    k_gemm_f16<<<dim3(2, 157), 256>>>(x, p_wpre, b_pre, p_h, NN, H1c, FF, FF, DDc, 1, 0);
    // 7,8: x_l (fp16 out) / x_r projections
    k_gemm_f16<<<dim3(13, 157), 256>>>(p_h, p_wl, b_l, p_xlh, NN, HCc, DDc, DDc, HCc, 0, 1);
    k_gemm_f16<<<dim3(13, 157), 256>>>(p_h, p_wr, b_r, p_xr, NN, HCc, DDc, DDc, HCc, 0, 0);
    // 9-12: CSR build
    k_zero_cnt<<<(NN + 255) / 256, 256>>>();
    k_count<<<(ETOT + 255) / 256, 256>>>(ei);
    k_scan<<<1, 1024>>>();
    k_fill<<<(ETOT + 255) / 256, 256>>>(ei);
    // 13: fused GATv2
    k_gat_fused<<<(NN * 32 + 127) / 128, 128>>>(att, gat_bias);
    // 14: GCN GEMM (fp16 out)
    k_gemm_f16<<<dim3(13, 157), 256>>>(p_g1, p_wg, nullptr, p_hgh, NN, HCc, HCc, HCc, HCc, 0, 1);
    // 15: GCN aggregation
    k_gcn_agg<<<(NN * 32 + 255) / 256, 256>>>(b_gcn);
    // 16-18: pooling + head
    k_gstart<<<1, 128>>>(batch);
    k_pool<<<GG, 256>>>(fw);
    k_head<<<GG, 128>>>(W_fc, b_fc, W_out, b_out, out);
}

// round 15
// speedup vs baseline: 2.1394x; 1.1017x over previous
#include <cuda_runtime.h>
#include <cuda_fp16.h>
#include <cstdint>

// ---------------- problem constants ----------------
#define NN    20000
#define EE    240000
#define ETOT  (EE + NN)        // edges + self loops = 260000
#define GG    64
#define FF    768
#define H1c   128
#define PEc   32
#define DDc   160              // H1 + PE
#define NHEAD 5
#define HCc   800              // NHEAD * DDc
#define H2c   128
#define OUTc  16
#define NEG_SLOPE 0.2f
#define NPAD  896              // padded N for HCc-wide weights (7*128)

// ---------------- device scratch (static, no allocs) ----------------
__device__ __align__(16) float d_h   [NN * DDc];
__device__ __align__(16) __half d_xlh[NN * HCc];   // x_l in fp16
__device__ __align__(16) float d_xr  [NN * HCc];
__device__ __align__(16) float d_g1  [NN * HCc];
__device__ __align__(16) __half d_hgh[NN * HCc];   // hg in fp16
__device__ __align__(16) float d_g2  [NN * HCc];
__device__ float d_dinv[NN];
__device__ int   d_cnt [NN];
__device__ int   d_rowptr[NN + 1];
__device__ int   d_csrc[ETOT];
__device__ int   d_gstart[GG + 1];
__device__ float d_pool[GG * 2 * HCc];

// transposed fp16 weights: [Npad][K] row-major
__device__ __align__(16) __half d_wpre[128 * FF];
__device__ __align__(16) __half d_wl  [NPAD * DDc];
__device__ __align__(16) __half d_wr  [NPAD * DDc];
__device__ __align__(16) __half d_wg  [NPAD * HCc];

// ---------------- CSR build ----------------
__global__ void k_zero_cnt() {
    int i = blockIdx.x * blockDim.x + threadIdx.x;
    if (i < NN) d_cnt[i] = 0;
}

__global__ void k_count(const int* __restrict__ ei) {
    int e = blockIdx.x * blockDim.x + threadIdx.x;
    if (e >= ETOT) return;
    int dst = (e < EE) ? ei[EE + e] : (e - EE);
    atomicAdd(&d_cnt[dst], 1);
}

// single-block scan, thread-local chunks of 20 -> one 1024-wide block scan
__global__ void k_scan() {
    __shared__ int sh[1024];
    const int CH = 20;
    int t = threadIdx.x;
    int base = t * CH;
    int loc[CH];
    int sum = 0;
    #pragma unroll
    for (int i = 0; i < CH; i++) {
        int idx = base + i;
        int v = 0;
        if (idx < NN) {
            v = d_cnt[idx];
            d_dinv[idx] = rsqrtf((float)v);   // deg >= 1 (self loop)
            d_cnt[idx] = 0;
        }
        loc[i] = sum;
        sum += v;
    }
    sh[t] = sum;
    __syncthreads();
    for (int off = 1; off < 1024; off <<= 1) {
        int add = (t >= off) ? sh[t - off] : 0;
        __syncthreads();
        sh[t] += add;
        __syncthreads();
    }
    int pre = (t == 0) ? 0 : sh[t - 1];
    #pragma unroll
    for (int i = 0; i < CH; i++) {
        int idx = base + i;
        if (idx < NN) d_rowptr[idx] = pre + loc[i];
    }
    if (t == 1023) d_rowptr[NN] = sh[1023];
}

__global__ void k_fill(const int* __restrict__ ei) {
    int e = blockIdx.x * blockDim.x + threadIdx.x;
    if (e >= ETOT) return;
    int src, dst;
    if (e < EE) { src = ei[e]; dst = ei[EE + e]; }
    else        { src = e - EE; dst = e - EE; }
    int pos = d_rowptr[dst] + atomicAdd(&d_cnt[dst], 1);
    d_csrc[pos] = src;
}

// ---------------- weight prep: transpose to fp16 ----------------
__global__ void k_prep(const float* __restrict__ W, __half* __restrict__ Wt,
                       int K, int Nc, int Npad) {
    __shared__ float tile[32][33];
    int k0 = blockIdx.x * 32, n0 = blockIdx.y * 32;
    int tx = threadIdx.x, ty = threadIdx.y;
    #pragma unroll
    for (int j = 0; j < 32; j += 8) {
        int k = k0 + ty + j, n = n0 + tx;
        tile[ty + j][tx] = (k < K && n < Nc) ? W[(size_t)k * Nc + n] : 0.f;
    }
    __syncthreads();
    #pragma unroll
    for (int j = 0; j < 32; j += 8) {
        int n = n0 + ty + j, k = k0 + tx;
        if (n < Npad && k < K)
            Wt[(size_t)n * K + k] = __float2half_rn(tile[tx][ty + j]);
    }
}

// ---------------- fp16 tensor-core GEMM ----------------
// CTA 128x128, BK=32, 256 thr, 8 warps (2m x 4n), warp tile 64x32, single buffer.
#define ASTR 12                  // uint2 per A m-row (8 used + 4 pad)
#define BSTR 132                 // uint2 per B k-row (128 used + 4 pad)

__device__ __forceinline__ uint32_t pk2h(float a, float b) {
    __half2 h = __floats2half2_rn(a, b);
    return *(uint32_t*)&h;
}

__device__ __forceinline__ void mma_f16(float c[4], uint32_t a0, uint32_t a1,
                                        uint32_t a2, uint32_t a3,
                                        uint32_t b0, uint32_t b1) {
    asm volatile(
        "mma.sync.aligned.m16n8k16.row.col.f32.f16.f16.f32 "
        "{%0,%1,%2,%3}, {%4,%5,%6,%7}, {%8,%9}, {%0,%1,%2,%3};\n"
        : "+f"(c[0]), "+f"(c[1]), "+f"(c[2]), "+f"(c[3])
        : "r"(a0), "r"(a1), "r"(a2), "r"(a3), "r"(b0), "r"(b1));
}

__global__ void __launch_bounds__(256, 2)
k_gemm_f16(const float* __restrict__ A, const __half* __restrict__ BT,
           const float* __restrict__ bias, void* __restrict__ Cv,
           int M, int Nc, int K, int lda, int ldc, int relu, int oh)
{
    __shared__ uint2 As[128 * ASTR];
    __shared__ uint2 Bs[8 * BSTR];

    const int t    = threadIdx.x;
    const int lane = t & 31;
    const int warp = t >> 5;
    const int wm   = warp >> 2;          // 0..1 -> m offset wm*64
    const int wn   = warp & 3;           // 0..3 -> n offset wn*32
    const int g    = lane >> 2;
    const int kq   = lane & 3;

    const int m0 = blockIdx.y * 128, n0 = blockIdx.x * 128;
    const float4 z4 = make_float4(0.f, 0.f, 0.f, 0.f);

    // fill maps
    const int ar = t >> 1, asb = t & 1;          // A: row 0..127, k16-half 0..1
    const int bnn = t & 127, bks = t >> 7;       // B: n 0..127, k16-half 0..1
    const bool a_ok = (m0 + ar) < M;

    float acc[4][4][4];
    #pragma unroll
    for (int i = 0; i < 4; i++)
        #pragma unroll
        for (int j = 0; j < 4; j++)
            #pragma unroll
            for (int q = 0; q < 4; q++) acc[i][j][q] = 0.f;

    const int nk = K >> 5;
    const float* arow = A + (size_t)(m0 + ar) * lda + asb * 16;
    const __half* brow = BT + (size_t)(n0 + bnn) * K + bks * 16;

    for (int kt = 0; kt < nk; kt++) {
        const int kb = kt << 5;
        __syncthreads();
        // ---- fill A ----
        {
            float4 ra[4];
            #pragma unroll
            for (int q = 0; q < 4; q++)
                ra[q] = a_ok ? *(const float4*)(arow + kb + q * 4) : z4;
            uint32_t p[8];
            #pragma unroll
            for (int q = 0; q < 4; q++) {
                p[2 * q]     = pk2h(ra[q].x, ra[q].y);
                p[2 * q + 1] = pk2h(ra[q].z, ra[q].w);
            }
            *(uint4*)&As[ar * ASTR + asb * 4]     = make_uint4(p[0], p[4], p[1], p[5]);
            *(uint4*)&As[ar * ASTR + asb * 4 + 2] = make_uint4(p[2], p[6], p[3], p[7]);
        }
        // ---- fill B ----
        {
            uint4 v0 = *(const uint4*)(brow + kb);
            uint4 v1 = *(const uint4*)(brow + kb + 8);
            const uint32_t* q0 = (const uint32_t*)&v0;
            const uint32_t* q1 = (const uint32_t*)&v1;
            #pragma unroll
            for (int k4 = 0; k4 < 4; k4++)
                Bs[(bks * 4 + k4) * BSTR + bnn] = make_uint2(q0[k4], q1[k4]);
        }
        __syncthreads();

        // ---- compute 2 k16 steps ----
        #pragma unroll
        for (int ks = 0; ks < 2; ks++) {
            uint2 pa[4][2];
            #pragma unroll
            for (int mi = 0; mi < 4; mi++) {
                int mr = wm * 64 + mi * 16;
                pa[mi][0] = As[(mr + g)     * ASTR + ks * 4 + kq];
                pa[mi][1] = As[(mr + 8 + g) * ASTR + ks * 4 + kq];
            }
            uint2 pb[4];
            #pragma unroll
            for (int ni = 0; ni < 4; ni++)
                pb[ni] = Bs[(ks * 4 + kq) * BSTR + wn * 32 + ni * 8 + g];
            #pragma unroll
            for (int mi = 0; mi < 4; mi++)
                #pragma unroll
                for (int ni = 0; ni < 4; ni++)
                    mma_f16(acc[mi][ni], pa[mi][0].x, pa[mi][1].x,
                            pa[mi][0].y, pa[mi][1].y, pb[ni].x, pb[ni].y);
        }
    }

    // ---- epilogue ----
    #pragma unroll
    for (int mi = 0; mi < 4; mi++) {
        #pragma unroll
        for (int half = 0; half < 2; half++) {
            int gm = m0 + wm * 64 + mi * 16 + g + half * 8;
            if (gm >= M) continue;
            #pragma unroll
            for (int ni = 0; ni < 4; ni++) {
                int gn = n0 + wn * 32 + ni * 8 + 2 * kq;
                if (gn >= Nc) continue;
                float v0 = acc[mi][ni][half * 2 + 0];
                float v1 = acc[mi][ni][half * 2 + 1];
                if (bias) { v0 += bias[gn]; v1 += bias[gn + 1]; }
                if (relu) { v0 = fmaxf(v0, 0.f); v1 = fmaxf(v1, 0.f); }
                if (oh) {
                    __half* Ch = (__half*)Cv;
                    *(uint32_t*)&Ch[(size_t)gm * ldc + gn] = pk2h(v0, v1);
                } else {
                    float* Cf = (float*)Cv;
                    float2 st; st.x = v0; st.y = v1;
                    *(float2*)&Cf[(size_t)gm * ldc + gn] = st;
                }
            }
        }
    }
}

// copy pe_enc into h[:, 128:160]
__global__ void k_pe(const float* __restrict__ pe) {
    int i = blockIdx.x * blockDim.x + threadIdx.x;
    if (i >= NN * PEc) return;
    int n = i / PEc, c = i % PEc;
    d_h[n * DDc + H1c + c] = pe[i];
}

// ---------------- fused GATv2 (no-max softmax, vectorized gathers) ----------------
// lane l, vec j: channels 128j+4l..+3 (j=0..5), tail channel 768+l.
// Head boundaries handled with per-j lane selects (160 = 1.25*128).
__global__ void __launch_bounds__(128)
k_gat_fused(const float* __restrict__ att, const float* __restrict__ gat_bias) {
    __shared__ float s_att[HCc];
    const int t = threadIdx.x;
    for (int k = t; k < HCc; k += 128) s_att[k] = att[k];
    __syncthreads();

    const int n = (blockIdx.x * 128 + t) >> 5;
    const int lane = t & 31;
    if (n >= NN) return;

    // xr in registers (float4 x6 + tail)
    float4 xrr[6];
    float xrt;
    {
        const float4* xr4 = (const float4*)(d_xr + (size_t)n * HCc);
        #pragma unroll
        for (int j = 0; j < 6; j++) xrr[j] = xr4[32 * j + lane];
        xrt = d_xr[(size_t)n * HCc + 768 + lane];
    }

    float acc[6][4], acct = 0.f, s[NHEAD];
    #pragma unroll
    for (int j = 0; j < 6; j++)
        #pragma unroll
        for (int q = 0; q < 4; q++) acc[j][q] = 0.f;
    #pragma unroll
    for (int h = 0; h < NHEAD; h++) s[h] = 0.f;

    const int beg = d_rowptr[n], end = d_rowptr[n + 1];
    for (int i = beg; i < end; i++) {
        const int src = d_csrc[i];
        const uint2* xl2 = (const uint2*)(d_xlh + (size_t)src * HCc);

        float xlr[6][4], xlt;
        float v[6], vt;
        #pragma unroll
        for (int j = 0; j < 6; j++) {
            uint2 u = xl2[32 * j + lane];
            float2 f01 = __half22float2(*(__half2*)&u.x);
            float2 f23 = __half22float2(*(__half2*)&u.y);
            xlr[j][0] = f01.x; xlr[j][1] = f01.y;
            xlr[j][2] = f23.x; xlr[j][3] = f23.y;
            float4 at = *(const float4*)&s_att[128 * j + 4 * lane];
            const float* xf = &xrr[j].x;
            float p = 0.f;
            float m0v = xlr[j][0] + xf[0]; m0v = (m0v > 0.f) ? m0v : NEG_SLOPE * m0v;
            float m1v = xlr[j][1] + xf[1]; m1v = (m1v > 0.f) ? m1v : NEG_SLOPE * m1v;
            float m2v = xlr[j][2] + xf[2]; m2v = (m2v > 0.f) ? m2v : NEG_SLOPE * m2v;
            float m3v = xlr[j][3] + xf[3]; m3v = (m3v > 0.f) ? m3v : NEG_SLOPE * m3v;
            p = m0v * at.x + m1v * at.y + m2v * at.z + m3v * at.w;
            v[j] = p;
        }
        xlt = __half2float(d_xlh[(size_t)src * HCc + 768 + lane]);
        {
            float mv = xlt + xrt; mv = (mv > 0.f) ? mv : NEG_SLOPE * mv;
            vt = mv * s_att[768 + lane];
        }

        float p0 = v[0] + ((lane <  8) ? v[1] : 0.f);
        float p1 = ((lane >=  8) ? v[1] : 0.f) + ((lane < 16) ? v[2] : 0.f);
        float p2 = ((lane >= 16) ? v[2] : 0.f) + ((lane < 24) ? v[3] : 0.f);
        float p3 = ((lane >= 24) ? v[3] : 0.f) + v[4];
        float p4 = v[5] + vt;
        #pragma unroll
        for (int off = 16; off > 0; off >>= 1) {
            p0 += __shfl_xor_sync(0xffffffffu, p0, off);
            p1 += __shfl_xor_sync(0xffffffffu, p1, off);
            p2 += __shfl_xor_sync(0xffffffffu, p2, off);
            p3 += __shfl_xor_sync(0xffffffffu, p3, off);
            p4 += __shfl_xor_sync(0xffffffffu, p4, off);
        }
        float e0 = __expf(p0), e1 = __expf(p1), e2 = __expf(p2);
        float e3 = __expf(p3), e4 = __expf(p4);
        s[0] += e0; s[1] += e1; s[2] += e2; s[3] += e3; s[4] += e4;

        float ej[6];
        ej[0] = e0;
        ej[1] = (lane <  8) ? e0 : e1;
        ej[2] = (lane < 16) ? e1 : e2;
        ej[3] = (lane < 24) ? e2 : e3;
        ej[4] = e3;
        ej[5] = e4;
        #pragma unroll
        for (int j = 0; j < 6; j++) {
            acc[j][0] += ej[j] * xlr[j][0];
            acc[j][1] += ej[j] * xlr[j][1];
            acc[j][2] += ej[j] * xlr[j][2];
            acc[j][3] += ej[j] * xlr[j][3];
        }
        acct += e4 * xlt;
    }

    float rs[NHEAD];
    #pragma unroll
    for (int h = 0; h < NHEAD; h++) rs[h] = 1.f / s[h];
    float rj[6];
    rj[0] = rs[0];
    rj[1] = (lane <  8) ? rs[0] : rs[1];
    rj[2] = (lane < 16) ? rs[1] : rs[2];
    rj[3] = (lane < 24) ? rs[2] : rs[3];
    rj[4] = rs[3];
    rj[5] = rs[4];

    float4* g14 = (float4*)(d_g1 + (size_t)n * HCc);
    #pragma unroll
    for (int j = 0; j < 6; j++) {
        float4 b = *(const float4*)&gat_bias[128 * j + 4 * lane];
        float4 o;
        o.x = fmaxf(acc[j][0] * rj[j] + b.x, 0.f);
        o.y = fmaxf(acc[j][1] * rj[j] + b.y, 0.f);
        o.z = fmaxf(acc[j][2] * rj[j] + b.z, 0.f);
        o.w = fmaxf(acc[j][3] * rj[j] + b.w, 0.f);
        g14[32 * j + lane] = o;
    }
    d_g1[(size_t)n * HCc + 768 + lane] = fmaxf(acct * rs[4] + gat_bias[768 + lane], 0.f);
}

// ---------------- GCN aggregation: hg fp16 uint2 loads ----------------
__global__ void k_gcn_agg(const float* __restrict__ b_gcn) {
    int n = (blockIdx.x * blockDim.x + threadIdx.x) >> 5;
    int lane = threadIdx.x & 31;
    if (n >= NN) return;
    float4 a[6];
    #pragma unroll
    for (int q = 0; q < 6; q++) a[q] = make_float4(0.f, 0.f, 0.f, 0.f);
    float at = 0.f;
    int beg = d_rowptr[n], end = d_rowptr[n + 1];
    float dn = d_dinv[n];
    for (int i = beg; i < end; i++) {
        int src = d_csrc[i];
        float w = d_dinv[src] * dn;
        const __half* hg = d_hgh + (size_t)src * HCc;
        #pragma unroll
        for (int q = 0; q < 6; q++) {
            uint2 u = ((const uint2*)hg)[32 * q + lane];
            float2 f01 = __half22float2(*(__half2*)&u.x);
            float2 f23 = __half22float2(*(__half2*)&u.y);
            a[q].x += w * f01.x; a[q].y += w * f01.y;
            a[q].z += w * f23.x; a[q].w += w * f23.y;
        }
        at += w * __half2float(hg[768 + lane]);
    }
    float* g2 = d_g2 + (size_t)n * HCc;
    #pragma unroll
    for (int q = 0; q < 6; q++) {
        int c = (32 * q + lane) * 4;
        float4 b = *(const float4*)&b_gcn[c];
        float4 o;
        o.x = fmaxf(a[q].x + b.x, 0.f); o.y = fmaxf(a[q].y + b.y, 0.f);
        o.z = fmaxf(a[q].z + b.z, 0.f); o.w = fmaxf(a[q].w + b.w, 0.f);
        *(float4*)&g2[c] = o;
    }
    g2[768 + lane] = fmaxf(at + b_gcn[768 + lane], 0.f);
}

// ---------------- graph boundaries (batch sorted) ----------------
__global__ void k_gstart(const int* __restrict__ batch) {
    int g = threadIdx.x;
    if (g > GG) return;
    int lo = 0, hi = NN;
    while (lo < hi) {
        int mid = (lo + hi) >> 1;
        if (batch[mid] < g) lo = mid + 1; else hi = mid;
    }
    d_gstart[g] = lo;
}

// ---------------- pooling: weighted mean + max per graph (float4) ----------------
__global__ void __launch_bounds__(256) k_pool(const float* __restrict__ fw) {
    int g = blockIdx.x;
    int t = threadIdx.x;
    int s = d_gstart[g], e2 = d_gstart[g + 1];
    if (t >= 200) return;
    float4 sum = make_float4(0.f, 0.f, 0.f, 0.f);
    float4 mx  = make_float4(0.f, 0.f, 0.f, 0.f);
    float ws = 0.f;
    for (int n = s; n < e2; n++) {
        float w = fw[n];
        ws += w;
        float4 v = ((const float4*)(d_g2 + (size_t)n * HCc))[t];
        sum.x += v.x * w; sum.y += v.y * w; sum.z += v.z * w; sum.w += v.w * w;
        mx.x = fmaxf(mx.x, v.x); mx.y = fmaxf(mx.y, v.y);
        mx.z = fmaxf(mx.z, v.z); mx.w = fmaxf(mx.w, v.w);
    }
    ws = fmaxf(ws, 1e-6f);
    float rws = 1.f / ws;
    float4 mn; mn.x = sum.x * rws; mn.y = sum.y * rws; mn.z = sum.z * rws; mn.w = sum.w * rws;
    ((float4*)(d_pool + g * 2 * HCc))[t] = mn;
    ((float4*)(d_pool + g * 2 * HCc + HCc))[t] = mx;
}

// ---------------- MLP head ----------------
__global__ void __launch_bounds__(128)
k_head(const float* __restrict__ W_fc, const float* __restrict__ b_fc,
       const float* __restrict__ W_out, const float* __restrict__ b_out,
       float* __restrict__ out)
{
    __shared__ float sp[2 * HCc];
    __shared__ float shid[H2c];
    int g = blockIdx.x, t = threadIdx.x;
    for (int k = t; k < 2 * HCc; k += 128) sp[k] = d_pool[g * 2 * HCc + k];
    __syncthreads();
    float acc = b_fc[t];
    for (int k = 0; k < 2 * HCc; k++) acc += sp[k] * W_fc[k * H2c + t];
    shid[t] = fmaxf(acc, 0.f);
    __syncthreads();
    if (t < OUTc) {
        float o = b_out[t];
        #pragma unroll
        for (int k = 0; k < H2c; k++) o += shid[k] * W_out[k * OUTc + t];
        out[g * OUTc + t] = fmaxf(o, 0.f);
    }
}

// ---------------- launch ----------------
extern "C" void kernel_launch(void* const* d_in, const int* in_sizes, int n_in,
                              void* d_out, int out_size)
{
    const float* x     = (const float*)d_in[0];
    const float* pe    = (const float*)d_in[1];
    const int*   ei    = (const int*)  d_in[2];
    const int*   batch = (const int*)  d_in[3];
    const float* fw    = (const float*)d_in[4];
    int wbase = (in_sizes[5] == 1) ? 6 : 5;
    const float* W_pre    = (const float*)d_in[wbase + 0];
    const float* b_pre    = (const float*)d_in[wbase + 1];
    const float* W_l      = (const float*)d_in[wbase + 2];
    const float* b_l      = (const float*)d_in[wbase + 3];
    const float* W_r      = (const float*)d_in[wbase + 4];
    const float* b_r      = (const float*)d_in[wbase + 5];
    const float* att      = (const float*)d_in[wbase + 6];
    const float* gat_bias = (const float*)d_in[wbase + 7];
    const float* W_gcn    = (const float*)d_in[wbase + 8];
    const float* b_gcn    = (const float*)d_in[wbase + 9];
    const float* W_fc     = (const float*)d_in[wbase + 10];
    const float* b_fc     = (const float*)d_in[wbase + 11];
    const float* W_out    = (const float*)d_in[wbase + 12];
    const float* b_out    = (const float*)d_in[wbase + 13];
    float* out = (float*)d_out;

    float* p_h  = nullptr; cudaGetSymbolAddress((void**)&p_h,  d_h);
    float* p_xr = nullptr; cudaGetSymbolAddress((void**)&p_xr, d_xr);
    float* p_g1 = nullptr; cudaGetSymbolAddress((void**)&p_g1, d_g1);
    __half* p_xlh = nullptr; cudaGetSymbolAddress((void**)&p_xlh, d_xlh);
    __half* p_hgh = nullptr; cudaGetSymbolAddress((void**)&p_hgh, d_hgh);
    __half *p_wpre, *p_wl, *p_wr, *p_wg;
    cudaGetSymbolAddress((void**)&p_wpre, d_wpre);
    cudaGetSymbolAddress((void**)&p_wl,   d_wl);
    cudaGetSymbolAddress((void**)&p_wr,   d_wr);
    cudaGetSymbolAddress((void**)&p_wg,   d_wg);

    dim3 tb(32, 8);
    // 1: pe copy
    k_pe<<<(NN * PEc + 255) / 256, 256>>>(pe);
    // 2-5: weight prep (transpose to fp16)
    k_prep<<<dim3((FF + 31) / 32, (128 + 31) / 32), tb>>>(W_pre, p_wpre, FF, H1c, 128);
    k_prep<<<dim3((DDc + 31) / 32, (NPAD + 31) / 32), tb>>>(W_l, p_wl, DDc, HCc, NPAD);
    k_prep<<<dim3((DDc + 31) / 32, (NPAD + 31) / 32), tb>>>(W_r, p_wr, DDc, HCc, NPAD);
    k_prep<<<dim3((HCc + 31) / 32, (NPAD + 31) / 32), tb>>>(W_gcn, p_wg, HCc, HCc, NPAD);
    // 6: pre-FC GEMM
    k_gemm_f16<<<dim3(1, 157), 256>>>(x, p_wpre, b_pre, p_h, NN, H1c, FF, FF, DDc, 1, 0);
    // 7,8: x_l (fp16 out) / x_r projections
    k_gemm_f16<<<dim3(7, 157), 256>>>(p_h, p_wl, b_l, p_xlh, NN, HCc, DDc, DDc, HCc, 0, 1);
    k_gemm_f16<<<dim3(7, 157), 256>>>(p_h, p_wr, b_r, p_xr, NN, HCc, DDc, DDc, HCc, 0, 0);
    // 9-12: CSR build
    k_zero_cnt<<<(NN + 255) / 256, 256>>>();
    k_count<<<(ETOT + 255) / 256, 256>>>(ei);
    k_scan<<<1, 1024>>>();
    k_fill<<<(ETOT + 255) / 256, 256>>>(ei);
    // 13: fused GATv2
    k_gat_fused<<<(NN * 32 + 127) / 128, 128>>>(att, gat_bias);
    // 14: GCN GEMM (fp16 out)
    k_gemm_f16<<<dim3(7, 157), 256>>>(p_g1, p_wg, nullptr, p_hgh, NN, HCc, HCc, HCc, HCc, 0, 1);
    // 15: GCN aggregation
    k_gcn_agg<<<(NN * 32 + 255) / 256, 256>>>(b_gcn);
    // 16-18: pooling + head
    k_gstart<<<1, 128>>>(batch);
    k_pool<<<GG, 256>>>(fw);
    k_head<<<GG, 128>>>(W_fc, b_fc, W_out, b_out, out);
}

// round 16
// speedup vs baseline: 2.3210x; 1.0849x over previous
#include <cuda_runtime.h>
#include <cuda_fp16.h>
#include <cstdint>

// ---------------- problem constants ----------------
#define NN    20000
#define EE    240000
#define ETOT  (EE + NN)        // edges + self loops = 260000
#define GG    64
#define FF    768
#define H1c   128
#define PEc   32
#define DDc   160              // H1 + PE
#define NHEAD 5
#define HCc   800              // NHEAD * DDc
#define H2c   128
#define OUTc  16
#define NEG_SLOPE 0.2f
#define NPAD  896              // padded N for HCc-wide weights (7*128)

// ---------------- device scratch (static, no allocs) ----------------
__device__ __align__(16) float d_h   [NN * DDc];
__device__ __align__(16) __half d_xlh[NN * HCc];   // x_l in fp16
__device__ __align__(16) float d_xr  [NN * HCc];
__device__ __align__(16) float d_g1  [NN * HCc];
__device__ __align__(16) __half d_hgh[NN * HCc];   // hg in fp16
__device__ __align__(16) float d_g2  [NN * HCc];
__device__ float d_dinv[NN];
__device__ int   d_cnt [NN];
__device__ int   d_rowptr[NN + 1];
__device__ int   d_csrc[ETOT];
__device__ int   d_gstart[GG + 1];
__device__ float d_pool[GG * 2 * HCc];

// transposed fp16 weights: [Npad][K] row-major
__device__ __align__(16) __half d_wpre[128 * FF];
__device__ __align__(16) __half d_wl  [NPAD * DDc];
__device__ __align__(16) __half d_wr  [NPAD * DDc];
__device__ __align__(16) __half d_wg  [NPAD * HCc];

// ---------------- CSR build ----------------
__global__ void k_zero_cnt() {
    int i = blockIdx.x * blockDim.x + threadIdx.x;
    if (i < NN) d_cnt[i] = 0;
}

__global__ void k_count(const int* __restrict__ ei) {
    int e = blockIdx.x * blockDim.x + threadIdx.x;
    if (e >= ETOT) return;
    int dst = (e < EE) ? ei[EE + e] : (e - EE);
    atomicAdd(&d_cnt[dst], 1);
}

// single-block scan, thread-local chunks of 20 -> one 1024-wide block scan
__global__ void k_scan() {
    __shared__ int sh[1024];
    const int CH = 20;
    int t = threadIdx.x;
    int base = t * CH;
    int loc[CH];
    int sum = 0;
    #pragma unroll
    for (int i = 0; i < CH; i++) {
        int idx = base + i;
        int v = 0;
        if (idx < NN) {
            v = d_cnt[idx];
            d_dinv[idx] = rsqrtf((float)v);   // deg >= 1 (self loop)
            d_cnt[idx] = 0;
        }
        loc[i] = sum;
        sum += v;
    }
    sh[t] = sum;
    __syncthreads();
    for (int off = 1; off < 1024; off <<= 1) {
        int add = (t >= off) ? sh[t - off] : 0;
        __syncthreads();
        sh[t] += add;
        __syncthreads();
    }
    int pre = (t == 0) ? 0 : sh[t - 1];
    #pragma unroll
    for (int i = 0; i < CH; i++) {
        int idx = base + i;
        if (idx < NN) d_rowptr[idx] = pre + loc[i];
    }
    if (t == 1023) d_rowptr[NN] = sh[1023];
}

__global__ void k_fill(const int* __restrict__ ei) {
    int e = blockIdx.x * blockDim.x + threadIdx.x;
    if (e >= ETOT) return;
    int src, dst;
    if (e < EE) { src = ei[e]; dst = ei[EE + e]; }
    else        { src = e - EE; dst = e - EE; }
    int pos = d_rowptr[dst] + atomicAdd(&d_cnt[dst], 1);
    d_csrc[pos] = src;
}

// ---------------- weight prep: transpose to fp16 ----------------
__global__ void k_prep(const float* __restrict__ W, __half* __restrict__ Wt,
                       int K, int Nc, int Npad) {
    __shared__ float tile[32][33];
    int k0 = blockIdx.x * 32, n0 = blockIdx.y * 32;
    int tx = threadIdx.x, ty = threadIdx.y;
    #pragma unroll
    for (int j = 0; j < 32; j += 8) {
        int k = k0 + ty + j, n = n0 + tx;
        tile[ty + j][tx] = (k < K && n < Nc) ? W[(size_t)k * Nc + n] : 0.f;
    }
    __syncthreads();
    #pragma unroll
    for (int j = 0; j < 32; j += 8) {
        int n = n0 + ty + j, k = k0 + tx;
        if (n < Npad && k < K)
            Wt[(size_t)n * K + k] = __float2half_rn(tile[tx][ty + j]);
    }
}

// ---------------- fp16 tensor-core GEMM ----------------
// CTA 128x128, BK=32, 256 thr, 8 warps (2m x 4n), warp tile 64x32.
// Two smem buffers, ONE __syncthreads per k-tile (fill(kt+1) overlaps compute(kt)).
#define ASTR 12                  // uint2 per A m-row (8 used + 4 pad)
#define BSTR 132                 // uint2 per B k-row (128 used + 4 pad)

__device__ __forceinline__ uint32_t pk2h(float a, float b) {
    __half2 h = __floats2half2_rn(a, b);
    return *(uint32_t*)&h;
}

__device__ __forceinline__ void mma_f16(float c[4], uint32_t a0, uint32_t a1,
                                        uint32_t a2, uint32_t a3,
                                        uint32_t b0, uint32_t b1) {
    asm volatile(
        "mma.sync.aligned.m16n8k16.row.col.f32.f16.f16.f32 "
        "{%0,%1,%2,%3}, {%4,%5,%6,%7}, {%8,%9}, {%0,%1,%2,%3};\n"
        : "+f"(c[0]), "+f"(c[1]), "+f"(c[2]), "+f"(c[3])
        : "r"(a0), "r"(a1), "r"(a2), "r"(a3), "r"(b0), "r"(b1));
}

__global__ void __launch_bounds__(256, 2)
k_gemm_f16(const float* __restrict__ A, const __half* __restrict__ BT,
           const float* __restrict__ bias, void* __restrict__ Cv,
           int M, int Nc, int K, int lda, int ldc, int relu, int oh)
{
    __shared__ uint2 As[2][128 * ASTR];
    __shared__ uint2 Bs[2][8 * BSTR];

    const int t    = threadIdx.x;
    const int lane = t & 31;
    const int warp = t >> 5;
    const int wm   = warp >> 2;          // 0..1 -> m offset wm*64
    const int wn   = warp & 3;           // 0..3 -> n offset wn*32
    const int g    = lane >> 2;
    const int kq   = lane & 3;

    const int m0 = blockIdx.y * 128, n0 = blockIdx.x * 128;
    const float4 z4 = make_float4(0.f, 0.f, 0.f, 0.f);

    // fill maps
    const int ar = t >> 1, asb = t & 1;          // A: row 0..127, k16-half 0..1
    const int bnn = t & 127, bks = t >> 7;       // B: n 0..127, k16-half 0..1
    const bool a_ok = (m0 + ar) < M;

    float acc[4][4][4];
    #pragma unroll
    for (int i = 0; i < 4; i++)
        #pragma unroll
        for (int j = 0; j < 4; j++)
            #pragma unroll
            for (int q = 0; q < 4; q++) acc[i][j][q] = 0.f;

    const int nk = K >> 5;
    const float* arow = A + (size_t)(m0 + ar) * lda + asb * 16;
    const __half* brow = BT + (size_t)(n0 + bnn) * K + bks * 16;

    for (int kt = 0; kt < nk; kt++) {
        const int kb = kt << 5;
        const int bf = kt & 1;
        // ---- fill A (buffer bf) ----
        {
            float4 ra[4];
            #pragma unroll
            for (int q = 0; q < 4; q++)
                ra[q] = a_ok ? *(const float4*)(arow + kb + q * 4) : z4;
            uint32_t p[8];
            #pragma unroll
            for (int q = 0; q < 4; q++) {
                p[2 * q]     = pk2h(ra[q].x, ra[q].y);
                p[2 * q + 1] = pk2h(ra[q].z, ra[q].w);
            }
            *(uint4*)&As[bf][ar * ASTR + asb * 4]     = make_uint4(p[0], p[4], p[1], p[5]);
            *(uint4*)&As[bf][ar * ASTR + asb * 4 + 2] = make_uint4(p[2], p[6], p[3], p[7]);
        }
        // ---- fill B (buffer bf) ----
        {
            uint4 v0 = *(const uint4*)(brow + kb);
            uint4 v1 = *(const uint4*)(brow + kb + 8);
            const uint32_t* q0 = (const uint32_t*)&v0;
            const uint32_t* q1 = (const uint32_t*)&v1;
            #pragma unroll
            for (int k4 = 0; k4 < 4; k4++)
                Bs[bf][(bks * 4 + k4) * BSTR + bnn] = make_uint2(q0[k4], q1[k4]);
        }
        __syncthreads();

        // ---- compute 2 k16 steps from buffer bf ----
        #pragma unroll
        for (int ks = 0; ks < 2; ks++) {
            uint2 pa[4][2];
            #pragma unroll
            for (int mi = 0; mi < 4; mi++) {
                int mr = wm * 64 + mi * 16;
                pa[mi][0] = As[bf][(mr + g)     * ASTR + ks * 4 + kq];
                pa[mi][1] = As[bf][(mr + 8 + g) * ASTR + ks * 4 + kq];
            }
            uint2 pb[4];
            #pragma unroll
            for (int ni = 0; ni < 4; ni++)
                pb[ni] = Bs[bf][(ks * 4 + kq) * BSTR + wn * 32 + ni * 8 + g];
            #pragma unroll
            for (int mi = 0; mi < 4; mi++)
                #pragma unroll
                for (int ni = 0; ni < 4; ni++)
                    mma_f16(acc[mi][ni], pa[mi][0].x, pa[mi][1].x,
                            pa[mi][0].y, pa[mi][1].y, pb[ni].x, pb[ni].y);
        }
    }

    // ---- epilogue ----
    #pragma unroll
    for (int mi = 0; mi < 4; mi++) {
        #pragma unroll
        for (int half = 0; half < 2; half++) {
            int gm = m0 + wm * 64 + mi * 16 + g + half * 8;
            if (gm >= M) continue;
            #pragma unroll
            for (int ni = 0; ni < 4; ni++) {
                int gn = n0 + wn * 32 + ni * 8 + 2 * kq;
                if (gn >= Nc) continue;
                float v0 = acc[mi][ni][half * 2 + 0];
                float v1 = acc[mi][ni][half * 2 + 1];
                if (bias) { v0 += bias[gn]; v1 += bias[gn + 1]; }
                if (relu) { v0 = fmaxf(v0, 0.f); v1 = fmaxf(v1, 0.f); }
                if (oh) {
                    __half* Ch = (__half*)Cv;
                    *(uint32_t*)&Ch[(size_t)gm * ldc + gn] = pk2h(v0, v1);
                } else {
                    float* Cf = (float*)Cv;
                    float2 st; st.x = v0; st.y = v1;
                    *(float2*)&Cf[(size_t)gm * ldc + gn] = st;
                }
            }
        }
    }
}

// copy pe_enc into h[:, 128:160]
__global__ void k_pe(const float* __restrict__ pe) {
    int i = blockIdx.x * blockDim.x + threadIdx.x;
    if (i >= NN * PEc) return;
    int n = i / PEc, c = i % PEc;
    d_h[n * DDc + H1c + c] = pe[i];
}

// ---------------- fused GATv2 (no-max softmax, vectorized gathers) ----------------
__global__ void __launch_bounds__(128)
k_gat_fused(const float* __restrict__ att, const float* __restrict__ gat_bias) {
    __shared__ float s_att[HCc];
    const int t = threadIdx.x;
    for (int k = t; k < HCc; k += 128) s_att[k] = att[k];
    __syncthreads();

    const int n = (blockIdx.x * 128 + t) >> 5;
    const int lane = t & 31;
    if (n >= NN) return;

    float4 xrr[6];
    float xrt;
    {
        const float4* xr4 = (const float4*)(d_xr + (size_t)n * HCc);
        #pragma unroll
        for (int j = 0; j < 6; j++) xrr[j] = xr4[32 * j + lane];
        xrt = d_xr[(size_t)n * HCc + 768 + lane];
    }

    float acc[6][4], acct = 0.f, s[NHEAD];
    #pragma unroll
    for (int j = 0; j < 6; j++)
        #pragma unroll
        for (int q = 0; q < 4; q++) acc[j][q] = 0.f;
    #pragma unroll
    for (int h = 0; h < NHEAD; h++) s[h] = 0.f;

    const int beg = d_rowptr[n], end = d_rowptr[n + 1];
    for (int i = beg; i < end; i++) {
        const int src = d_csrc[i];
        const uint2* xl2 = (const uint2*)(d_xlh + (size_t)src * HCc);

        float xlr[6][4], xlt;
        float v[6], vt;
        #pragma unroll
        for (int j = 0; j < 6; j++) {
            uint2 u = xl2[32 * j + lane];
            float2 f01 = __half22float2(*(__half2*)&u.x);
            float2 f23 = __half22float2(*(__half2*)&u.y);
            xlr[j][0] = f01.x; xlr[j][1] = f01.y;
            xlr[j][2] = f23.x; xlr[j][3] = f23.y;
            float4 at = *(const float4*)&s_att[128 * j + 4 * lane];
            const float* xf = &xrr[j].x;
            float m0v = xlr[j][0] + xf[0]; m0v = (m0v > 0.f) ? m0v : NEG_SLOPE * m0v;
            float m1v = xlr[j][1] + xf[1]; m1v = (m1v > 0.f) ? m1v : NEG_SLOPE * m1v;
            float m2v = xlr[j][2] + xf[2]; m2v = (m2v > 0.f) ? m2v : NEG_SLOPE * m2v;
            float m3v = xlr[j][3] + xf[3]; m3v = (m3v > 0.f) ? m3v : NEG_SLOPE * m3v;
            v[j] = m0v * at.x + m1v * at.y + m2v * at.z + m3v * at.w;
        }
        xlt = __half2float(d_xlh[(size_t)src * HCc + 768 + lane]);
        {
            float mv = xlt + xrt; mv = (mv > 0.f) ? mv : NEG_SLOPE * mv;
            vt = mv * s_att[768 + lane];
        }

        float p0 = v[0] + ((lane <  8) ? v[1] : 0.f);
        float p1 = ((lane >=  8) ? v[1] : 0.f) + ((lane < 16) ? v[2] : 0.f);
        float p2 = ((lane >= 16) ? v[2] : 0.f) + ((lane < 24) ? v[3] : 0.f);
        float p3 = ((lane >= 24) ? v[3] : 0.f) + v[4];
        float p4 = v[5] + vt;
        #pragma unroll
        for (int off = 16; off > 0; off >>= 1) {
            p0 += __shfl_xor_sync(0xffffffffu, p0, off);
            p1 += __shfl_xor_sync(0xffffffffu, p1, off);
            p2 += __shfl_xor_sync(0xffffffffu, p2, off);
            p3 += __shfl_xor_sync(0xffffffffu, p3, off);
            p4 += __shfl_xor_sync(0xffffffffu, p4, off);
        }
        float e0 = __expf(p0), e1 = __expf(p1), e2 = __expf(p2);
        float e3 = __expf(p3), e4 = __expf(p4);
        s[0] += e0; s[1] += e1; s[2] += e2; s[3] += e3; s[4] += e4;

        float ej[6];
        ej[0] = e0;
        ej[1] = (lane <  8) ? e0 : e1;
        ej[2] = (lane < 16) ? e1 : e2;
        ej[3] = (lane < 24) ? e2 : e3;
        ej[4] = e3;
        ej[5] = e4;
        #pragma unroll
        for (int j = 0; j < 6; j++) {
            acc[j][0] += ej[j] * xlr[j][0];
            acc[j][1] += ej[j] * xlr[j][1];
            acc[j][2] += ej[j] * xlr[j][2];
            acc[j][3] += ej[j] * xlr[j][3];
        }
        acct += e4 * xlt;
    }

    float rs[NHEAD];
    #pragma unroll
    for (int h = 0; h < NHEAD; h++) rs[h] = 1.f / s[h];
    float rj[6];
    rj[0] = rs[0];
    rj[1] = (lane <  8) ? rs[0] : rs[1];
    rj[2] = (lane < 16) ? rs[1] : rs[2];
    rj[3] = (lane < 24) ? rs[2] : rs[3];
    rj[4] = rs[3];
    rj[5] = rs[4];

    float4* g14 = (float4*)(d_g1 + (size_t)n * HCc);
    #pragma unroll
    for (int j = 0; j < 6; j++) {
        float4 b = *(const float4*)&gat_bias[128 * j + 4 * lane];
        float4 o;
        o.x = fmaxf(acc[j][0] * rj[j] + b.x, 0.f);
        o.y = fmaxf(acc[j][1] * rj[j] + b.y, 0.f);
        o.z = fmaxf(acc[j][2] * rj[j] + b.z, 0.f);
        o.w = fmaxf(acc[j][3] * rj[j] + b.w, 0.f);
        g14[32 * j + lane] = o;
    }
    d_g1[(size_t)n * HCc + 768 + lane] = fmaxf(acct * rs[4] + gat_bias[768 + lane], 0.f);
}

// ---------------- GCN aggregation: hg fp16 uint2 loads ----------------
__global__ void k_gcn_agg(const float* __restrict__ b_gcn) {
    int n = (blockIdx.x * blockDim.x + threadIdx.x) >> 5;
    int lane = threadIdx.x & 31;
    if (n >= NN) return;
    float4 a[6];
    #pragma unroll
    for (int q = 0; q < 6; q++) a[q] = make_float4(0.f, 0.f, 0.f, 0.f);
    float at = 0.f;
    int beg = d_rowptr[n], end = d_rowptr[n + 1];
    float dn = d_dinv[n];
    for (int i = beg; i < end; i++) {
        int src = d_csrc[i];
        float w = d_dinv[src] * dn;
        const __half* hg = d_hgh + (size_t)src * HCc;
        #pragma unroll
        for (int q = 0; q < 6; q++) {
            uint2 u = ((const uint2*)hg)[32 * q + lane];
            float2 f01 = __half22float2(*(__half2*)&u.x);
            float2 f23 = __half22float2(*(__half2*)&u.y);
            a[q].x += w * f01.x; a[q].y += w * f01.y;
            a[q].z += w * f23.x; a[q].w += w * f23.y;
        }
        at += w * __half2float(hg[768 + lane]);
    }
    float* g2 = d_g2 + (size_t)n * HCc;
    #pragma unroll
    for (int q = 0; q < 6; q++) {
        int c = (32 * q + lane) * 4;
        float4 b = *(const float4*)&b_gcn[c];
        float4 o;
        o.x = fmaxf(a[q].x + b.x, 0.f); o.y = fmaxf(a[q].y + b.y, 0.f);
        o.z = fmaxf(a[q].z + b.z, 0.f); o.w = fmaxf(a[q].w + b.w, 0.f);
        *(float4*)&g2[c] = o;
    }
    g2[768 + lane] = fmaxf(at + b_gcn[768 + lane], 0.f);
}

// ---------------- graph boundaries (batch sorted) ----------------
__global__ void k_gstart(const int* __restrict__ batch) {
    int g = threadIdx.x;
    if (g > GG) return;
    int lo = 0, hi = NN;
    while (lo < hi) {
        int mid = (lo + hi) >> 1;
        if (batch[mid] < g) lo = mid + 1; else hi = mid;
    }
    d_gstart[g] = lo;
}

// ---------------- pooling: weighted mean + max per graph (float4) ----------------
__global__ void __launch_bounds__(256) k_pool(const float* __restrict__ fw) {
    int g = blockIdx.x;
    int t = threadIdx.x;
    int s = d_gstart[g], e2 = d_gstart[g + 1];
    if (t >= 200) return;
    float4 sum = make_float4(0.f, 0.f, 0.f, 0.f);
    float4 mx  = make_float4(0.f, 0.f, 0.f, 0.f);
    float ws = 0.f;
    for (int n = s; n < e2; n++) {
        float w = fw[n];
        ws += w;
        float4 v = ((const float4*)(d_g2 + (size_t)n * HCc))[t];
        sum.x += v.x * w; sum.y += v.y * w; sum.z += v.z * w; sum.w += v.w * w;
        mx.x = fmaxf(mx.x, v.x); mx.y = fmaxf(mx.y, v.y);
        mx.z = fmaxf(mx.z, v.z); mx.w = fmaxf(mx.w, v.w);
    }
    ws = fmaxf(ws, 1e-6f);
    float rws = 1.f / ws;
    float4 mn; mn.x = sum.x * rws; mn.y = sum.y * rws; mn.z = sum.z * rws; mn.w = sum.w * rws;
    ((float4*)(d_pool + g * 2 * HCc))[t] = mn;
    ((float4*)(d_pool + g * 2 * HCc + HCc))[t] = mx;
}

// ---------------- MLP head ----------------
__global__ void __launch_bounds__(128)
k_head(const float* __restrict__ W_fc, const float* __restrict__ b_fc,
       const float* __restrict__ W_out, const float* __restrict__ b_out,
       float* __restrict__ out)
{
    __shared__ float sp[2 * HCc];
    __shared__ float shid[H2c];
    int g = blockIdx.x, t = threadIdx.x;
    for (int k = t; k < 2 * HCc; k += 128) sp[k] = d_pool[g * 2 * HCc + k];
    __syncthreads();
    float acc = b_fc[t];
    for (int k = 0; k < 2 * HCc; k++) acc += sp[k] * W_fc[k * H2c + t];
    shid[t] = fmaxf(acc, 0.f);
    __syncthreads();
    if (t < OUTc) {
        float o = b_out[t];
        #pragma unroll
        for (int k = 0; k < H2c; k++) o += shid[k] * W_out[k * OUTc + t];
        out[g * OUTc + t] = fmaxf(o, 0.f);
    }
}

// ---------------- launch ----------------
extern "C" void kernel_launch(void* const* d_in, const int* in_sizes, int n_in,
                              void* d_out, int out_size)
{
    const float* x     = (const float*)d_in[0];
    const float* pe    = (const float*)d_in[1];
    const int*   ei    = (const int*)  d_in[2];
    const int*   batch = (const int*)  d_in[3];
    const float* fw    = (const float*)d_in[4];
    int wbase = (in_sizes[5] == 1) ? 6 : 5;
    const float* W_pre    = (const float*)d_in[wbase + 0];
    const float* b_pre    = (const float*)d_in[wbase + 1];
    const float* W_l      = (const float*)d_in[wbase + 2];
    const float* b_l      = (const float*)d_in[wbase + 3];
    const float* W_r      = (const float*)d_in[wbase + 4];
    const float* b_r      = (const float*)d_in[wbase + 5];
    const float* att      = (const float*)d_in[wbase + 6];
    const float* gat_bias = (const float*)d_in[wbase + 7];
    const float* W_gcn    = (const float*)d_in[wbase + 8];
    const float* b_gcn    = (const float*)d_in[wbase + 9];
    const float* W_fc     = (const float*)d_in[wbase + 10];
    const float* b_fc     = (const float*)d_in[wbase + 11];
    const float* W_out    = (const float*)d_in[wbase + 12];
    const float* b_out    = (const float*)d_in[wbase + 13];
    float* out = (float*)d_out;

    float* p_h  = nullptr; cudaGetSymbolAddress((void**)&p_h,  d_h);
    float* p_xr = nullptr; cudaGetSymbolAddress((void**)&p_xr, d_xr);
    float* p_g1 = nullptr; cudaGetSymbolAddress((void**)&p_g1, d_g1);
    __half* p_xlh = nullptr; cudaGetSymbolAddress((void**)&p_xlh, d_xlh);
    __half* p_hgh = nullptr; cudaGetSymbolAddress((void**)&p_hgh, d_hgh);
    __half *p_wpre, *p_wl, *p_wr, *p_wg;
    cudaGetSymbolAddress((void**)&p_wpre, d_wpre);
    cudaGetSymbolAddress((void**)&p_wl,   d_wl);
    cudaGetSymbolAddress((void**)&p_wr,   d_wr);
    cudaGetSymbolAddress((void**)&p_wg,   d_wg);

    // one-time stream/event setup (outside capture: first call is the
    // uncaptured correctness run)
    static cudaStream_t s_aux = nullptr;
    static cudaEvent_t ev_fork = nullptr, ev_join = nullptr;
    if (!s_aux) {
        cudaStreamCreateWithFlags(&s_aux, cudaStreamNonBlocking);
        cudaEventCreateWithFlags(&ev_fork, cudaEventDisableTiming);
        cudaEventCreateWithFlags(&ev_join, cudaEventDisableTiming);
    }

    // ---- fork: CSR build + gstart run on s_aux, overlapping the GEMM chain ----
    cudaEventRecord(ev_fork, 0);
    cudaStreamWaitEvent(s_aux, ev_fork, 0);
    k_zero_cnt<<<(NN + 255) / 256, 256, 0, s_aux>>>();
    k_count<<<(ETOT + 255) / 256, 256, 0, s_aux>>>(ei);
    k_scan<<<1, 1024, 0, s_aux>>>();
    k_fill<<<(ETOT + 255) / 256, 256, 0, s_aux>>>(ei);
    k_gstart<<<1, 128, 0, s_aux>>>(batch);
    cudaEventRecord(ev_join, s_aux);

    // ---- main stream: pe, weight prep, GEMMs ----
    dim3 tb(32, 8);
    k_pe<<<(NN * PEc + 255) / 256, 256>>>(pe);
    k_prep<<<dim3((FF + 31) / 32, (128 + 31) / 32), tb>>>(W_pre, p_wpre, FF, H1c, 128);
    k_prep<<<dim3((DDc + 31) / 32, (NPAD + 31) / 32), tb>>>(W_l, p_wl, DDc, HCc, NPAD);
    k_prep<<<dim3((DDc + 31) / 32, (NPAD + 31) / 32), tb>>>(W_r, p_wr, DDc, HCc, NPAD);
    k_prep<<<dim3((HCc + 31) / 32, (NPAD + 31) / 32), tb>>>(W_gcn, p_wg, HCc, HCc, NPAD);
    k_gemm_f16<<<dim3(1, 157), 256>>>(x, p_wpre, b_pre, p_h, NN, H1c, FF, FF, DDc, 1, 0);
    k_gemm_f16<<<dim3(7, 157), 256>>>(p_h, p_wl, b_l, p_xlh, NN, HCc, DDc, DDc, HCc, 0, 1);
    k_gemm_f16<<<dim3(7, 157), 256>>>(p_h, p_wr, b_r, p_xr, NN, HCc, DDc, DDc, HCc, 0, 0);

    // ---- join: gat_fused needs CSR ----
    cudaStreamWaitEvent(0, ev_join, 0);
    k_gat_fused<<<(NN * 32 + 127) / 128, 128>>>(att, gat_bias);
    k_gemm_f16<<<dim3(7, 157), 256>>>(p_g1, p_wg, nullptr, p_hgh, NN, HCc, HCc, HCc, HCc, 0, 1);
    k_gcn_agg<<<(NN * 32 + 255) / 256, 256>>>(b_gcn);
    k_pool<<<GG, 256>>>(fw);
    k_head<<<GG, 128>>>(W_fc, b_fc, W_out, b_out, out);
}

// round 17
// speedup vs baseline: 2.5420x; 1.0952x over previous
#include <cuda_runtime.h>
#include <cuda_fp16.h>
#include <cstdint>

// ---------------- problem constants ----------------
#define NN    20000
#define EE    240000
#define ETOT  (EE + NN)        // edges + self loops = 260000
#define GG    64
#define FF    768
#define H1c   128
#define PEc   32
#define DDc   160              // H1 + PE
#define NHEAD 5
#define HCc   800              // NHEAD * DDc
#define H2c   128
#define OUTc  16
#define NEG_SLOPE 0.2f
#define XLR   1600             // concat(x_l, x_r) row width
#define NPADG 896              // padded N for W_gcn (7*128)
#define NPADLR 1664            // padded N for concat W_l|W_r (13*128)

// ---------------- device scratch (static, no allocs) ----------------
__device__ __align__(16) __half d_hh  [NN * DDc];    // h in fp16
__device__ __align__(16) __half d_xlrh[NN * XLR];    // [x_l | x_r] fp16
__device__ __align__(16) __half d_g1h [NN * HCc];    // g1 fp16
__device__ __align__(16) __half d_hgh [NN * HCc];    // hg fp16
__device__ __align__(16) float  d_g2  [NN * HCc];
__device__ float d_dinv[NN];
__device__ int   d_cnt [NN];
__device__ int   d_rowptr[NN + 1];
__device__ int   d_csrc[ETOT];
__device__ int   d_gstart[GG + 1];
__device__ float d_pool[GG * 2 * HCc];
__device__ float d_blr[XLR];                          // concat bias

// transposed fp16 weights: [Npad][K] row-major
__device__ __align__(16) __half d_wpre[128 * FF];
__device__ __align__(16) __half d_wlr [NPADLR * DDc];
__device__ __align__(16) __half d_wg  [NPADG * HCc];

// ---------------- CSR build ----------------
__global__ void k_zero_cnt() {
    int i = blockIdx.x * blockDim.x + threadIdx.x;
    if (i < NN) d_cnt[i] = 0;
}

__global__ void k_count(const int* __restrict__ ei) {
    int e = blockIdx.x * blockDim.x + threadIdx.x;
    if (e >= ETOT) return;
    int dst = (e < EE) ? ei[EE + e] : (e - EE);
    atomicAdd(&d_cnt[dst], 1);
}

// single-block scan, thread-local chunks of 20 -> one 1024-wide block scan
__global__ void k_scan() {
    __shared__ int sh[1024];
    const int CH = 20;
    int t = threadIdx.x;
    int base = t * CH;
    int loc[CH];
    int sum = 0;
    #pragma unroll
    for (int i = 0; i < CH; i++) {
        int idx = base + i;
        int v = 0;
        if (idx < NN) {
            v = d_cnt[idx];
            d_dinv[idx] = rsqrtf((float)v);   // deg >= 1 (self loop)
            d_cnt[idx] = 0;
        }
        loc[i] = sum;
        sum += v;
    }
    sh[t] = sum;
    __syncthreads();
    for (int off = 1; off < 1024; off <<= 1) {
        int add = (t >= off) ? sh[t - off] : 0;
        __syncthreads();
        sh[t] += add;
        __syncthreads();
    }
    int pre = (t == 0) ? 0 : sh[t - 1];
    #pragma unroll
    for (int i = 0; i < CH; i++) {
        int idx = base + i;
        if (idx < NN) d_rowptr[idx] = pre + loc[i];
    }
    if (t == 1023) d_rowptr[NN] = sh[1023];
}

__global__ void k_fill(const int* __restrict__ ei) {
    int e = blockIdx.x * blockDim.x + threadIdx.x;
    if (e >= ETOT) return;
    int src, dst;
    if (e < EE) { src = ei[e]; dst = ei[EE + e]; }
    else        { src = e - EE; dst = e - EE; }
    int pos = d_rowptr[dst] + atomicAdd(&d_cnt[dst], 1);
    d_csrc[pos] = src;
}

// ---------------- weight prep: transpose to fp16 ----------------
__global__ void k_prep(const float* __restrict__ W, __half* __restrict__ Wt,
                       int K, int Nc, int Npad) {
    __shared__ float tile[32][33];
    int k0 = blockIdx.x * 32, n0 = blockIdx.y * 32;
    int tx = threadIdx.x, ty = threadIdx.y;
    #pragma unroll
    for (int j = 0; j < 32; j += 8) {
        int k = k0 + ty + j, n = n0 + tx;
        tile[ty + j][tx] = (k < K && n < Nc) ? W[(size_t)k * Nc + n] : 0.f;
    }
    __syncthreads();
    #pragma unroll
    for (int j = 0; j < 32; j += 8) {
        int n = n0 + ty + j, k = k0 + tx;
        if (n < Npad && k < K)
            Wt[(size_t)n * K + k] = __float2half_rn(tile[tx][ty + j]);
    }
}

// concat biases
__global__ void k_cat(const float* __restrict__ a, const float* __restrict__ b) {
    int i = blockIdx.x * blockDim.x + threadIdx.x;
    if (i < HCc) { d_blr[i] = a[i]; d_blr[HCc + i] = b[i]; }
}

// ---------------- fp16 tensor-core GEMM (templated M-tile, fp16/fp32 A) ----------
// CTA tile (MIC*32) x 128, BK=32, 256 thr, 8 warps (2m x 4n).
// Two smem buffers, ONE __syncthreads per k-tile.
#define ASTR 12
#define BSTR 132

__device__ __forceinline__ uint32_t pk2h(float a, float b) {
    __half2 h = __floats2half2_rn(a, b);
    return *(uint32_t*)&h;
}

__device__ __forceinline__ void mma_f16(float c[4], uint32_t a0, uint32_t a1,
                                        uint32_t a2, uint32_t a3,
                                        uint32_t b0, uint32_t b1) {
    asm volatile(
        "mma.sync.aligned.m16n8k16.row.col.f32.f16.f16.f32 "
        "{%0,%1,%2,%3}, {%4,%5,%6,%7}, {%8,%9}, {%0,%1,%2,%3};\n"
        : "+f"(c[0]), "+f"(c[1]), "+f"(c[2]), "+f"(c[3])
        : "r"(a0), "r"(a1), "r"(a2), "r"(a3), "r"(b0), "r"(b1));
}

template <int MIC, int AH>
__global__ void __launch_bounds__(256, 2)
k_gemm_f16(const void* __restrict__ Av, const __half* __restrict__ BT,
           const float* __restrict__ bias, void* __restrict__ Cv,
           int M, int Nc, int K, int lda, int ldc, int relu, int oh)
{
    __shared__ uint2 As[2][128 * ASTR];
    __shared__ uint2 Bs[2][8 * BSTR];

    const int t    = threadIdx.x;
    const int lane = t & 31;
    const int warp = t >> 5;
    const int wm   = warp >> 2;          // 0..1 -> m offset wm*(MIC*16)
    const int wn   = warp & 3;           // 0..3 -> n offset wn*32
    const int g    = lane >> 2;
    const int kq   = lane & 3;

    const int R  = MIC * 32;
    const int m0 = blockIdx.y * R, n0 = blockIdx.x * 128;

    // fill maps
    const int ar = t >> 1, asb = t & 1;          // A: row, k16-half
    const bool a_fill = (t < R * 2);
    const int bnn = t & 127, bks = t >> 7;       // B: n, k16-half
    const bool a_ok = a_fill && ((m0 + ar) < M);

    float acc[MIC][4][4];
    #pragma unroll
    for (int i = 0; i < MIC; i++)
        #pragma unroll
        for (int j = 0; j < 4; j++)
            #pragma unroll
            for (int q = 0; q < 4; q++) acc[i][j][q] = 0.f;

    const int nk = K >> 5;
    const float*  arf = (const float*)Av + (a_fill ? (size_t)(m0 + ar) * lda : 0) + asb * 16;
    const __half* arh = (const __half*)Av + (a_fill ? (size_t)(m0 + ar) * lda : 0) + asb * 16;
    const __half* brow = BT + (size_t)(n0 + bnn) * K + bks * 16;
    const float4 z4 = make_float4(0.f, 0.f, 0.f, 0.f);
    const uint4  zu = make_uint4(0u, 0u, 0u, 0u);

    for (int kt = 0; kt < nk; kt++) {
        const int kb = kt << 5;
        const int bf = kt & 1;
        // ---- fill A (buffer bf) ----
        if (a_fill) {
            if (AH) {
                uint4 v0 = a_ok ? *(const uint4*)(arh + kb) : zu;
                uint4 v1 = a_ok ? *(const uint4*)(arh + kb + 8) : zu;
                const uint32_t* q0 = (const uint32_t*)&v0;
                const uint32_t* q1 = (const uint32_t*)&v1;
                #pragma unroll
                for (int k4 = 0; k4 < 4; k4++)
                    As[bf][ar * ASTR + asb * 4 + k4] = make_uint2(q0[k4], q1[k4]);
            } else {
                float4 ra[4];
                #pragma unroll
                for (int q = 0; q < 4; q++)
                    ra[q] = a_ok ? *(const float4*)(arf + kb + q * 4) : z4;
                uint32_t p[8];
                #pragma unroll
                for (int q = 0; q < 4; q++) {
                    p[2 * q]     = pk2h(ra[q].x, ra[q].y);
                    p[2 * q + 1] = pk2h(ra[q].z, ra[q].w);
                }
                *(uint4*)&As[bf][ar * ASTR + asb * 4]     = make_uint4(p[0], p[4], p[1], p[5]);
                *(uint4*)&As[bf][ar * ASTR + asb * 4 + 2] = make_uint4(p[2], p[6], p[3], p[7]);
            }
        }
        // ---- fill B (buffer bf) ----
        {
            uint4 v0 = *(const uint4*)(brow + kb);
            uint4 v1 = *(const uint4*)(brow + kb + 8);
            const uint32_t* q0 = (const uint32_t*)&v0;
            const uint32_t* q1 = (const uint32_t*)&v1;
            #pragma unroll
            for (int k4 = 0; k4 < 4; k4++)
                Bs[bf][(bks * 4 + k4) * BSTR + bnn] = make_uint2(q0[k4], q1[k4]);
        }
        __syncthreads();

        // ---- compute 2 k16 steps from buffer bf ----
        #pragma unroll
        for (int ks = 0; ks < 2; ks++) {
            uint2 pa[MIC][2];
            #pragma unroll
            for (int mi = 0; mi < MIC; mi++) {
                int mr = wm * (MIC * 16) + mi * 16;
                pa[mi][0] = As[bf][(mr + g)     * ASTR + ks * 4 + kq];
                pa[mi][1] = As[bf][(mr + 8 + g) * ASTR + ks * 4 + kq];
            }
            uint2 pb[4];
            #pragma unroll
            for (int ni = 0; ni < 4; ni++)
                pb[ni] = Bs[bf][(ks * 4 + kq) * BSTR + wn * 32 + ni * 8 + g];
            #pragma unroll
            for (int mi = 0; mi < MIC; mi++)
                #pragma unroll
                for (int ni = 0; ni < 4; ni++)
                    mma_f16(acc[mi][ni], pa[mi][0].x, pa[mi][1].x,
                            pa[mi][0].y, pa[mi][1].y, pb[ni].x, pb[ni].y);
        }
    }

    // ---- epilogue ----
    #pragma unroll
    for (int mi = 0; mi < MIC; mi++) {
        #pragma unroll
        for (int half = 0; half < 2; half++) {
            int gm = m0 + wm * (MIC * 16) + mi * 16 + g + half * 8;
            if (gm >= M) continue;
            #pragma unroll
            for (int ni = 0; ni < 4; ni++) {
                int gn = n0 + wn * 32 + ni * 8 + 2 * kq;
                if (gn >= Nc) continue;
                float v0 = acc[mi][ni][half * 2 + 0];
                float v1 = acc[mi][ni][half * 2 + 1];
                if (bias) { v0 += bias[gn]; v1 += bias[gn + 1]; }
                if (relu) { v0 = fmaxf(v0, 0.f); v1 = fmaxf(v1, 0.f); }
                if (oh) {
                    __half* Ch = (__half*)Cv;
                    *(uint32_t*)&Ch[(size_t)gm * ldc + gn] = pk2h(v0, v1);
                } else {
                    float* Cf = (float*)Cv;
                    float2 st; st.x = v0; st.y = v1;
                    *(float2*)&Cf[(size_t)gm * ldc + gn] = st;
                }
            }
        }
    }
}

// copy pe_enc into h[:, 128:160] (fp16)
__global__ void k_pe(const float* __restrict__ pe) {
    int i = blockIdx.x * blockDim.x + threadIdx.x;
    if (i >= NN * PEc) return;
    int n = i / PEc, c = i % PEc;
    d_hh[n * DDc + H1c + c] = __float2half_rn(pe[i]);
}

// ---------------- fused GATv2 (no-max softmax, fp16 xl/xr, fp16 g1 out) ---------
__global__ void __launch_bounds__(128)
k_gat_fused(const float* __restrict__ att, const float* __restrict__ gat_bias) {
    __shared__ float s_att[HCc];
    const int t = threadIdx.x;
    for (int k = t; k < HCc; k += 128) s_att[k] = att[k];
    __syncthreads();

    const int n = (blockIdx.x * 128 + t) >> 5;
    const int lane = t & 31;
    if (n >= NN) return;

    // xr (fp16) -> registers
    float xrr[6][4];
    float xrt;
    {
        const uint2* xr2 = (const uint2*)(d_xlrh + (size_t)n * XLR + HCc);
        #pragma unroll
        for (int j = 0; j < 6; j++) {
            uint2 u = xr2[32 * j + lane];
            float2 f01 = __half22float2(*(__half2*)&u.x);
            float2 f23 = __half22float2(*(__half2*)&u.y);
            xrr[j][0] = f01.x; xrr[j][1] = f01.y;
            xrr[j][2] = f23.x; xrr[j][3] = f23.y;
        }
        xrt = __half2float(d_xlrh[(size_t)n * XLR + HCc + 768 + lane]);
    }

    float acc[6][4], acct = 0.f, s[NHEAD];
    #pragma unroll
    for (int j = 0; j < 6; j++)
        #pragma unroll
        for (int q = 0; q < 4; q++) acc[j][q] = 0.f;
    #pragma unroll
    for (int h = 0; h < NHEAD; h++) s[h] = 0.f;

    const int beg = d_rowptr[n], end = d_rowptr[n + 1];
    for (int i = beg; i < end; i++) {
        const int src = d_csrc[i];
        const uint2* xl2 = (const uint2*)(d_xlrh + (size_t)src * XLR);

        float xlr[6][4], xlt;
        float v[6], vt;
        #pragma unroll
        for (int j = 0; j < 6; j++) {
            uint2 u = xl2[32 * j + lane];
            float2 f01 = __half22float2(*(__half2*)&u.x);
            float2 f23 = __half22float2(*(__half2*)&u.y);
            xlr[j][0] = f01.x; xlr[j][1] = f01.y;
            xlr[j][2] = f23.x; xlr[j][3] = f23.y;
            float4 at = *(const float4*)&s_att[128 * j + 4 * lane];
            float m0v = xlr[j][0] + xrr[j][0]; m0v = (m0v > 0.f) ? m0v : NEG_SLOPE * m0v;
            float m1v = xlr[j][1] + xrr[j][1]; m1v = (m1v > 0.f) ? m1v : NEG_SLOPE * m1v;
            float m2v = xlr[j][2] + xrr[j][2]; m2v = (m2v > 0.f) ? m2v : NEG_SLOPE * m2v;
            float m3v = xlr[j][3] + xrr[j][3]; m3v = (m3v > 0.f) ? m3v : NEG_SLOPE * m3v;
            v[j] = m0v * at.x + m1v * at.y + m2v * at.z + m3v * at.w;
        }
        xlt = __half2float(d_xlrh[(size_t)src * XLR + 768 + lane]);
        {
            float mv = xlt + xrt; mv = (mv > 0.f) ? mv : NEG_SLOPE * mv;
            vt = mv * s_att[768 + lane];
        }

        float p0 = v[0] + ((lane <  8) ? v[1] : 0.f);
        float p1 = ((lane >=  8) ? v[1] : 0.f) + ((lane < 16) ? v[2] : 0.f);
        float p2 = ((lane >= 16) ? v[2] : 0.f) + ((lane < 24) ? v[3] : 0.f);
        float p3 = ((lane >= 24) ? v[3] : 0.f) + v[4];
        float p4 = v[5] + vt;
        #pragma unroll
        for (int off = 16; off > 0; off >>= 1) {
            p0 += __shfl_xor_sync(0xffffffffu, p0, off);
            p1 += __shfl_xor_sync(0xffffffffu, p1, off);
            p2 += __shfl_xor_sync(0xffffffffu, p2, off);
            p3 += __shfl_xor_sync(0xffffffffu, p3, off);
            p4 += __shfl_xor_sync(0xffffffffu, p4, off);
        }
        float e0 = __expf(p0), e1 = __expf(p1), e2 = __expf(p2);
        float e3 = __expf(p3), e4 = __expf(p4);
        s[0] += e0; s[1] += e1; s[2] += e2; s[3] += e3; s[4] += e4;

        float ej[6];
        ej[0] = e0;
        ej[1] = (lane <  8) ? e0 : e1;
        ej[2] = (lane < 16) ? e1 : e2;
        ej[3] = (lane < 24) ? e2 : e3;
        ej[4] = e3;
        ej[5] = e4;
        #pragma unroll
        for (int j = 0; j < 6; j++) {
            acc[j][0] += ej[j] * xlr[j][0];
            acc[j][1] += ej[j] * xlr[j][1];
            acc[j][2] += ej[j] * xlr[j][2];
            acc[j][3] += ej[j] * xlr[j][3];
        }
        acct += e4 * xlt;
    }

    float rs[NHEAD];
    #pragma unroll
    for (int h = 0; h < NHEAD; h++) rs[h] = 1.f / s[h];
    float rj[6];
    rj[0] = rs[0];
    rj[1] = (lane <  8) ? rs[0] : rs[1];
    rj[2] = (lane < 16) ? rs[1] : rs[2];
    rj[3] = (lane < 24) ? rs[2] : rs[3];
    rj[4] = rs[3];
    rj[5] = rs[4];

    uint2* g12 = (uint2*)(d_g1h + (size_t)n * HCc);
    #pragma unroll
    for (int j = 0; j < 6; j++) {
        float4 b = *(const float4*)&gat_bias[128 * j + 4 * lane];
        float o0 = fmaxf(acc[j][0] * rj[j] + b.x, 0.f);
        float o1 = fmaxf(acc[j][1] * rj[j] + b.y, 0.f);
        float o2 = fmaxf(acc[j][2] * rj[j] + b.z, 0.f);
        float o3 = fmaxf(acc[j][3] * rj[j] + b.w, 0.f);
        g12[32 * j + lane] = make_uint2(pk2h(o0, o1), pk2h(o2, o3));
    }
    d_g1h[(size_t)n * HCc + 768 + lane] =
        __float2half_rn(fmaxf(acct * rs[4] + gat_bias[768 + lane], 0.f));
}

// ---------------- GCN aggregation: hg fp16 uint2 loads ----------------
__global__ void k_gcn_agg(const float* __restrict__ b_gcn) {
    int n = (blockIdx.x * blockDim.x + threadIdx.x) >> 5;
    int lane = threadIdx.x & 31;
    if (n >= NN) return;
    float4 a[6];
    #pragma unroll
    for (int q = 0; q < 6; q++) a[q] = make_float4(0.f, 0.f, 0.f, 0.f);
    float at = 0.f;
    int beg = d_rowptr[n], end = d_rowptr[n + 1];
    float dn = d_dinv[n];
    for (int i = beg; i < end; i++) {
        int src = d_csrc[i];
        float w = d_dinv[src] * dn;
        const __half* hg = d_hgh + (size_t)src * HCc;
        #pragma unroll
        for (int q = 0; q < 6; q++) {
            uint2 u = ((const uint2*)hg)[32 * q + lane];
            float2 f01 = __half22float2(*(__half2*)&u.x);
            float2 f23 = __half22float2(*(__half2*)&u.y);
            a[q].x += w * f01.x; a[q].y += w * f01.y;
            a[q].z += w * f23.x; a[q].w += w * f23.y;
        }
        at += w * __half2float(hg[768 + lane]);
    }
    float* g2 = d_g2 + (size_t)n * HCc;
    #pragma unroll
    for (int q = 0; q < 6; q++) {
        int c = (32 * q + lane) * 4;
        float4 b = *(const float4*)&b_gcn[c];
        float4 o;
        o.x = fmaxf(a[q].x + b.x, 0.f); o.y = fmaxf(a[q].y + b.y, 0.f);
        o.z = fmaxf(a[q].z + b.z, 0.f); o.w = fmaxf(a[q].w + b.w, 0.f);
        *(float4*)&g2[c] = o;
    }
    g2[768 + lane] = fmaxf(at + b_gcn[768 + lane], 0.f);
}

// ---------------- graph boundaries (batch sorted) ----------------
__global__ void k_gstart(const int* __restrict__ batch) {
    int g = threadIdx.x;
    if (g > GG) return;
    int lo = 0, hi = NN;
    while (lo < hi) {
        int mid = (lo + hi) >> 1;
        if (batch[mid] < g) lo = mid + 1; else hi = mid;
    }
    d_gstart[g] = lo;
}

// ---------------- pooling: weighted mean + max per graph (float4) ----------------
__global__ void __launch_bounds__(256) k_pool(const float* __restrict__ fw) {
    int g = blockIdx.x;
    int t = threadIdx.x;
    int s = d_gstart[g], e2 = d_gstart[g + 1];
    if (t >= 200) return;
    float4 sum = make_float4(0.f, 0.f, 0.f, 0.f);
    float4 mx  = make_float4(0.f, 0.f, 0.f, 0.f);
    float ws = 0.f;
    for (int n = s; n < e2; n++) {
        float w = fw[n];
        ws += w;
        float4 v = ((const float4*)(d_g2 + (size_t)n * HCc))[t];
        sum.x += v.x * w; sum.y += v.y * w; sum.z += v.z * w; sum.w += v.w * w;
        mx.x = fmaxf(mx.x, v.x); mx.y = fmaxf(mx.y, v.y);
        mx.z = fmaxf(mx.z, v.z); mx.w = fmaxf(mx.w, v.w);
    }
    ws = fmaxf(ws, 1e-6f);
    float rws = 1.f / ws;
    float4 mn; mn.x = sum.x * rws; mn.y = sum.y * rws; mn.z = sum.z * rws; mn.w = sum.w * rws;
    ((float4*)(d_pool + g * 2 * HCc))[t] = mn;
    ((float4*)(d_pool + g * 2 * HCc + HCc))[t] = mx;
}

// ---------------- MLP head ----------------
__global__ void __launch_bounds__(128)
k_head(const float* __restrict__ W_fc, const float* __restrict__ b_fc,
       const float* __restrict__ W_out, const float* __restrict__ b_out,
       float* __restrict__ out)
{
    __shared__ float sp[2 * HCc];
    __shared__ float shid[H2c];
    int g = blockIdx.x, t = threadIdx.x;
    for (int k = t; k < 2 * HCc; k += 128) sp[k] = d_pool[g * 2 * HCc + k];
    __syncthreads();
    float acc = b_fc[t];
    for (int k = 0; k < 2 * HCc; k++) acc += sp[k] * W_fc[k * H2c + t];
    shid[t] = fmaxf(acc, 0.f);
    __syncthreads();
    if (t < OUTc) {
        float o = b_out[t];
        #pragma unroll
        for (int k = 0; k < H2c; k++) o += shid[k] * W_out[k * OUTc + t];
        out[g * OUTc + t] = fmaxf(o, 0.f);
    }
}

// ---------------- launch ----------------
extern "C" void kernel_launch(void* const* d_in, const int* in_sizes, int n_in,
                              void* d_out, int out_size)
{
    const float* x     = (const float*)d_in[0];
    const float* pe    = (const float*)d_in[1];
    const int*   ei    = (const int*)  d_in[2];
    const int*   batch = (const int*)  d_in[3];
    const float* fw    = (const float*)d_in[4];
    int wbase = (in_sizes[5] == 1) ? 6 : 5;
    const float* W_pre    = (const float*)d_in[wbase + 0];
    const float* b_pre    = (const float*)d_in[wbase + 1];
    const float* W_l      = (const float*)d_in[wbase + 2];
    const float* b_l      = (const float*)d_in[wbase + 3];
    const float* W_r      = (const float*)d_in[wbase + 4];
    const float* b_r      = (const float*)d_in[wbase + 5];
    const float* att      = (const float*)d_in[wbase + 6];
    const float* gat_bias = (const float*)d_in[wbase + 7];
    const float* W_gcn    = (const float*)d_in[wbase + 8];
    const float* b_gcn    = (const float*)d_in[wbase + 9];
    const float* W_fc     = (const float*)d_in[wbase + 10];
    const float* b_fc     = (const float*)d_in[wbase + 11];
    const float* W_out    = (const float*)d_in[wbase + 12];
    const float* b_out    = (const float*)d_in[wbase + 13];
    float* out = (float*)d_out;

    __half* p_hh;   cudaGetSymbolAddress((void**)&p_hh,   d_hh);
    __half* p_xlrh; cudaGetSymbolAddress((void**)&p_xlrh, d_xlrh);
    __half* p_g1h;  cudaGetSymbolAddress((void**)&p_g1h,  d_g1h);
    __half* p_hgh;  cudaGetSymbolAddress((void**)&p_hgh,  d_hgh);
    __half *p_wpre, *p_wlr, *p_wg;
    cudaGetSymbolAddress((void**)&p_wpre, d_wpre);
    cudaGetSymbolAddress((void**)&p_wlr,  d_wlr);
    cudaGetSymbolAddress((void**)&p_wg,   d_wg);
    float* p_blr;   cudaGetSymbolAddress((void**)&p_blr,  d_blr);

    static cudaStream_t s_aux = nullptr;
    static cudaEvent_t ev_fork = nullptr, ev_join = nullptr;
    if (!s_aux) {
        cudaStreamCreateWithFlags(&s_aux, cudaStreamNonBlocking);
        cudaEventCreateWithFlags(&ev_fork, cudaEventDisableTiming);
        cudaEventCreateWithFlags(&ev_join, cudaEventDisableTiming);
    }

    // ---- fork: CSR build + gstart on aux stream ----
    cudaEventRecord(ev_fork, 0);
    cudaStreamWaitEvent(s_aux, ev_fork, 0);
    k_zero_cnt<<<(NN + 255) / 256, 256, 0, s_aux>>>();
    k_count<<<(ETOT + 255) / 256, 256, 0, s_aux>>>(ei);
    k_scan<<<1, 1024, 0, s_aux>>>();
    k_fill<<<(ETOT + 255) / 256, 256, 0, s_aux>>>(ei);
    k_gstart<<<1, 128, 0, s_aux>>>(batch);
    cudaEventRecord(ev_join, s_aux);

    // ---- main stream ----
    dim3 tb(32, 8);
    k_pe<<<(NN * PEc + 255) / 256, 256>>>(pe);
    k_prep<<<dim3((FF + 31) / 32, 4), tb>>>(W_pre, p_wpre, FF, H1c, 128);
    k_prep<<<dim3((DDc + 31) / 32, 25), tb>>>(W_l, p_wlr, DDc, HCc, HCc);
    k_prep<<<dim3((DDc + 31) / 32, 27), tb>>>(W_r, p_wlr + (size_t)HCc * DDc, DDc, HCc, NPADLR - HCc);
    k_prep<<<dim3((HCc + 31) / 32, (NPADG + 31) / 32), tb>>>(W_gcn, p_wg, HCc, HCc, NPADG);
    k_cat<<<(HCc + 255) / 256, 256>>>(b_l, b_r);
    // pre-FC: 64-row tiles -> 313 CTAs (fills the chip)
    k_gemm_f16<2, 0><<<dim3(1, (NN + 63) / 64), 256>>>(
        x, p_wpre, b_pre, p_hh, NN, H1c, FF, FF, DDc, 1, 1);
    // merged x_l | x_r projection (fp16 A, fp16 out)
    k_gemm_f16<4, 1><<<dim3(NPADLR / 128, (NN + 127) / 128), 256>>>(
        p_hh, p_wlr, p_blr, p_xlrh, NN, XLR, DDc, DDc, XLR, 0, 1);

    // ---- join: gat needs CSR ----
    cudaStreamWaitEvent(0, ev_join, 0);
    k_gat_fused<<<(NN * 32 + 127) / 128, 128>>>(att, gat_bias);
    k_gemm_f16<4, 1><<<dim3(NPADG / 128, (NN + 127) / 128), 256>>>(
        p_g1h, p_wg, nullptr, p_hgh, NN, HCc, HCc, HCc, HCc, 0, 1);
    k_gcn_agg<<<(NN * 32 + 255) / 256, 256>>>(b_gcn);
    k_pool<<<GG, 256>>>(fw);
    k_head<<<GG, 128>>>(W_fc, b_fc, W_out, b_out, out);
}